// round 1
// baseline (speedup 1.0000x reference)
#include <cuda_runtime.h>
#include <cuda_fp16.h>

// Problem constants
#define BB 8
#define TT 4096
#define NE 16
#define HH 64

// Scratch (device globals: allocation-free per harness rules)
__device__ float  g_M[NE * NE];                       // Wq @ Wk^T   (16x16)
__device__ float  g_U[BB * TT * NE];                  // U[b,s,e] = sum_e' M[e,e'] x[b,s,e']
__device__ float  g_Zpart[BB * 4 * TT];               // partial column sums of E
__device__ float  g_XZ[BB * TT * NE];                 // x[b,s,e] / Z[b,s]
__device__ __half g_E[(size_t)BB * TT * TT];          // exp(scores^(-1/16)), 268MB

// ---------------------------------------------------------------------------
// Kernel 1: M = Wq @ Wk^T  (16x16, K=64). One block, 256 threads.
__global__ void m_kernel(const float* __restrict__ Wq, const float* __restrict__ Wk) {
    int e  = threadIdx.x >> 4;
    int e2 = threadIdx.x & 15;
    float s = 0.f;
#pragma unroll
    for (int h = 0; h < HH; ++h)
        s += Wq[e * HH + h] * Wk[e2 * HH + h];
    g_M[e * NE + e2] = s;
}

// ---------------------------------------------------------------------------
// Kernel 2: U[b,s,:] = M @ x[b,s,:]   (one thread per (b,s))
__global__ void __launch_bounds__(128) u_kernel(const float* __restrict__ x) {
    __shared__ float Ms[NE * NE];
    for (int i = threadIdx.x; i < NE * NE; i += 128) Ms[i] = g_M[i];
    __syncthreads();

    int gs = blockIdx.x * 128 + threadIdx.x;   // 0 .. B*T-1
    float xv[NE];
    const float4* xp = (const float4*)(x + (size_t)gs * NE);
#pragma unroll
    for (int q = 0; q < 4; ++q) {
        float4 v = xp[q];
        xv[q * 4 + 0] = v.x; xv[q * 4 + 1] = v.y;
        xv[q * 4 + 2] = v.z; xv[q * 4 + 3] = v.w;
    }
#pragma unroll
    for (int j = 0; j < NE; ++j) {
        float u = 0.f;
#pragma unroll
        for (int k = 0; k < NE; ++k) u += Ms[j * NE + k] * xv[k];
        g_U[(size_t)gs * NE + j] = u;
    }
}

// ---------------------------------------------------------------------------
// Kernel 3 (pass A): E[t,s] = exp((x[t]·u[s])^(-1/16)); partial Z[s] sums.
// grid = (T/128 s-tiles, 4 t-chunks, B), block = 128 threads (one s each).
__global__ void __launch_bounds__(128) passA_kernel(const float* __restrict__ x) {
    __shared__ float sx[128 * NE];   // 8KB tile of x rows

    const int b  = blockIdx.z;
    const int tc = blockIdx.y;               // t-chunk: 1024 rows
    const int s  = blockIdx.x * 128 + threadIdx.x;

    // u[s] in registers
    const float4* up = (const float4*)(g_U + ((size_t)b * TT + s) * NE);
    const float4 ua = up[0], ub = up[1], uc = up[2], ud = up[3];

    float zacc = 0.f;
    const size_t Ebase = ((size_t)b * TT) * TT + s;
    const int t0 = tc * 1024;

    for (int tb = t0; tb < t0 + 1024; tb += 128) {
        const float* xb = x + ((size_t)b * TT + tb) * NE;
        for (int i = threadIdx.x; i < 128 * NE; i += 128) sx[i] = xb[i];
        __syncthreads();

#pragma unroll 4
        for (int tt = 0; tt < 128; ++tt) {
            const float4* xr = (const float4*)(sx + tt * NE);
            float4 xa = xr[0], xb4 = xr[1], xc = xr[2], xd = xr[3];
            float d = xa.x * ua.x + xa.y * ua.y + xa.z * ua.z + xa.w * ua.w;
            d += xb4.x * ub.x + xb4.y * ub.y + xb4.z * ub.z + xb4.w * ub.w;
            d += xc.x * uc.x + xc.y * uc.y + xc.z * uc.z + xc.w * uc.w;
            d += xd.x * ud.x + xd.y * ud.y + xd.z * ud.z + xd.w * ud.w;
            // p = d^(-1/16); ev = exp(p).  d is strictly positive (~20..150).
            float p  = __expf(-0.0625f * __logf(d));
            float ev = __expf(p);
            zacc += ev;
            g_E[Ebase + (size_t)(tb + tt) * TT] = __float2half_rn(ev);
        }
        __syncthreads();
    }
    g_Zpart[(b * 4 + tc) * TT + s] = zacc;
}

// ---------------------------------------------------------------------------
// Kernel 4: Z[b,s] = sum of 4 partials (fixed order, deterministic);
//           XZ[b,s,e] = x[b,s,e] / Z[b,s]
__global__ void __launch_bounds__(128) z_kernel(const float* __restrict__ x) {
    int gs = blockIdx.x * 128 + threadIdx.x;   // b*T + s
    int b  = gs >> 12;
    int s  = gs & (TT - 1);
    float z = (g_Zpart[(b * 4 + 0) * TT + s] + g_Zpart[(b * 4 + 1) * TT + s]) +
              (g_Zpart[(b * 4 + 2) * TT + s] + g_Zpart[(b * 4 + 3) * TT + s]);
    float inv = 1.0f / z;
#pragma unroll
    for (int e = 0; e < NE; ++e)
        g_XZ[(size_t)gs * NE + e] = x[(size_t)gs * NE + e] * inv;
}

// ---------------------------------------------------------------------------
// Kernel 5 (pass B): G[t,:] = sum_s E[t,s] * XZ[s,:]; out[t,:] = G[t,:] @ Wk.
// grid = (T/128 row-tiles, B), block = 128 threads (32 row-groups x 4 e-groups,
// each thread owns a 4x4 register tile of G).
__global__ void __launch_bounds__(128) passB_kernel(const float* __restrict__ Wk,
                                                    float* __restrict__ out) {
    __shared__ unsigned int Es[128 * 33];    // 128 rows x 32 half2, padded (+1)
    __shared__ float xzs[64 * NE];           // 64 s-rows of XZ
    __shared__ float wks[NE * HH];           // Wk
    __shared__ float Gs[128 * 17];           // G tile, padded

    const int b  = blockIdx.y;
    const int t0 = blockIdx.x * 128;
    const int tid = threadIdx.x;

    for (int i = tid; i < NE * HH; i += 128) wks[i] = Wk[i];

    const int rg = tid >> 2;   // row group 0..31 -> rows rg*4 .. rg*4+3
    const int eg = tid & 3;    // e group   0..3  -> e    eg*4 .. eg*4+3

    float acc[4][4];
#pragma unroll
    for (int i = 0; i < 4; ++i)
#pragma unroll
        for (int j = 0; j < 4; ++j) acc[i][j] = 0.f;

    const size_t Erow0 = ((size_t)b * TT + t0) * TT;   // half units

    for (int sc = 0; sc < TT; sc += 64) {
        // stage E tile: 128 rows x 64 halves (as 32 half2 per row)
        const unsigned int* src = (const unsigned int*)(g_E + Erow0 + sc);
        for (int i = tid; i < 128 * 32; i += 128) {
            int row = i >> 5, c = i & 31;
            Es[row * 33 + c] = src[(size_t)row * (TT / 2) + c];
        }
        // stage XZ tile: 64 x 16 floats (contiguous)
        const float* xsrc = g_XZ + ((size_t)b * TT + sc) * NE;
        for (int i = tid; i < 64 * NE; i += 128) xzs[i] = xsrc[i];
        __syncthreads();

#pragma unroll 4
        for (int c = 0; c < 32; ++c) {
            float4 w0 = *(const float4*)(xzs + (2 * c) * NE + eg * 4);
            float4 w1 = *(const float4*)(xzs + (2 * c + 1) * NE + eg * 4);
#pragma unroll
            for (int i = 0; i < 4; ++i) {
                unsigned int eh = Es[(rg * 4 + i) * 33 + c];
                float2 ef = __half22float2(*(const __half2*)&eh);
                acc[i][0] += ef.x * w0.x + ef.y * w1.x;
                acc[i][1] += ef.x * w0.y + ef.y * w1.y;
                acc[i][2] += ef.x * w0.z + ef.y * w1.z;
                acc[i][3] += ef.x * w0.w + ef.y * w1.w;
            }
        }
        __syncthreads();
    }

    // spill G to smem
#pragma unroll
    for (int i = 0; i < 4; ++i)
#pragma unroll
        for (int j = 0; j < 4; ++j)
            Gs[(rg * 4 + i) * 17 + eg * 4 + j] = acc[i][j];
    __syncthreads();

    // epilogue: out[t, h] = sum_e G[t,e] * Wk[e,h]
    for (int idx = tid; idx < 128 * HH; idx += 128) {
        int r = idx >> 6, h = idx & 63;
        float sum = 0.f;
#pragma unroll
        for (int e = 0; e < NE; ++e) sum += Gs[r * 17 + e] * wks[e * HH + h];
        out[((size_t)b * TT + t0 + r) * HH + h] = sum;
    }
}

// ---------------------------------------------------------------------------
extern "C" void kernel_launch(void* const* d_in, const int* in_sizes, int n_in,
                              void* d_out, int out_size) {
    const float* x  = (const float*)d_in[0];   // [B, T, 16]
    const float* Wq = (const float*)d_in[1];   // [16, 64]
    const float* Wk = (const float*)d_in[2];   // [16, 64]
    // d_in[3] = Wv, unused (reference uses Wk for values)
    float* out = (float*)d_out;                // [B, T, 64]

    m_kernel<<<1, 256>>>(Wq, Wk);
    u_kernel<<<(BB * TT) / 128, 128>>>(x);
    passA_kernel<<<dim3(TT / 128, 4, BB), 128>>>(x);
    z_kernel<<<(BB * TT) / 128, 128>>>(x);
    passB_kernel<<<dim3(TT / 128, BB), 128>>>(Wk, out);
}

// round 2
// speedup vs baseline: 1.6158x; 1.6158x over previous
#include <cuda_runtime.h>
#include <cuda_fp16.h>
#include <cstdint>

// Problem constants
#define BB 8
#define TT 4096
#define NE 16
#define HH 64

// Scratch (device globals: allocation-free per harness rules)
__device__ float  g_M[NE * NE];                       // Wq @ Wk^T   (16x16)
__device__ float  g_U[BB * TT * NE];                  // U[b,s,e] = sum_e' M[e,e'] x[b,s,e']
__device__ float  g_Zpart[BB * 4 * TT];               // partial column sums of E
__device__ __half g_XZh[BB * NE * TT];                // [b][e][s] = x[b,s,e] / Z[b,s]  (fp16, transposed)
__device__ __half g_E[(size_t)BB * TT * TT];          // exp(scores^(-1/16)), 268MB

// ---------------------------------------------------------------------------
// Kernel 1: M = Wq @ Wk^T  (16x16, K=64). One block, 256 threads.
__global__ void m_kernel(const float* __restrict__ Wq, const float* __restrict__ Wk) {
    int e  = threadIdx.x >> 4;
    int e2 = threadIdx.x & 15;
    float s = 0.f;
#pragma unroll
    for (int h = 0; h < HH; ++h)
        s += Wq[e * HH + h] * Wk[e2 * HH + h];
    g_M[e * NE + e2] = s;
}

// ---------------------------------------------------------------------------
// Kernel 2: U[b,s,:] = M @ x[b,s,:]   (one thread per (b,s))
__global__ void __launch_bounds__(128) u_kernel(const float* __restrict__ x) {
    __shared__ float Ms[NE * NE];
    for (int i = threadIdx.x; i < NE * NE; i += 128) Ms[i] = g_M[i];
    __syncthreads();

    int gs = blockIdx.x * 128 + threadIdx.x;   // 0 .. B*T-1
    float xv[NE];
    const float4* xp = (const float4*)(x + (size_t)gs * NE);
#pragma unroll
    for (int q = 0; q < 4; ++q) {
        float4 v = xp[q];
        xv[q * 4 + 0] = v.x; xv[q * 4 + 1] = v.y;
        xv[q * 4 + 2] = v.z; xv[q * 4 + 3] = v.w;
    }
#pragma unroll
    for (int j = 0; j < NE; ++j) {
        float u = 0.f;
#pragma unroll
        for (int k = 0; k < NE; ++k) u += Ms[j * NE + k] * xv[k];
        g_U[(size_t)gs * NE + j] = u;
    }
}

// ---------------------------------------------------------------------------
// Kernel 3 (pass A): E[t,s] = exp((x[t]·u[s])^(-1/16)); partial Z[s] sums.
// grid = (T/128 s-tiles, 4 t-chunks, B), block = 128 threads (one s each).
__global__ void __launch_bounds__(128) passA_kernel(const float* __restrict__ x) {
    __shared__ float sx[128 * NE];   // 8KB tile of x rows

    const int b  = blockIdx.z;
    const int tc = blockIdx.y;               // t-chunk: 1024 rows
    const int s  = blockIdx.x * 128 + threadIdx.x;

    // u[s] in registers
    const float4* up = (const float4*)(g_U + ((size_t)b * TT + s) * NE);
    const float4 ua = up[0], ub = up[1], uc = up[2], ud = up[3];

    float zacc = 0.f;
    const size_t Ebase = ((size_t)b * TT) * TT + s;
    const int t0 = tc * 1024;

    for (int tb = t0; tb < t0 + 1024; tb += 128) {
        const float* xb = x + ((size_t)b * TT + tb) * NE;
        for (int i = threadIdx.x; i < 128 * NE; i += 128) sx[i] = xb[i];
        __syncthreads();

#pragma unroll 4
        for (int tt = 0; tt < 128; ++tt) {
            const float4* xr = (const float4*)(sx + tt * NE);
            float4 xa = xr[0], xb4 = xr[1], xc = xr[2], xd = xr[3];
            float d = xa.x * ua.x + xa.y * ua.y + xa.z * ua.z + xa.w * ua.w;
            d += xb4.x * ub.x + xb4.y * ub.y + xb4.z * ub.z + xb4.w * ub.w;
            d += xc.x * uc.x + xc.y * uc.y + xc.z * uc.z + xc.w * uc.w;
            d += xd.x * ud.x + xd.y * ud.y + xd.z * ud.z + xd.w * ud.w;
            // p = d^(-1/16); ev = exp(p).  d is strictly positive (~20..150).
            float p  = __expf(-0.0625f * __logf(d));
            float ev = __expf(p);
            zacc += ev;
            g_E[Ebase + (size_t)(tb + tt) * TT] = __float2half_rn(ev);
        }
        __syncthreads();
    }
    g_Zpart[(b * 4 + tc) * TT + s] = zacc;
}

// ---------------------------------------------------------------------------
// Kernel 4: Z[b,s] = sum of 4 partials (fixed order, deterministic);
//           XZh[b,e,s] = fp16( x[b,s,e] / Z[b,s] )   (transposed for mma B operand)
__global__ void __launch_bounds__(128) z_kernel(const float* __restrict__ x) {
    int gs = blockIdx.x * 128 + threadIdx.x;   // b*T + s
    int b  = gs >> 12;
    int s  = gs & (TT - 1);
    float z = (g_Zpart[(b * 4 + 0) * TT + s] + g_Zpart[(b * 4 + 1) * TT + s]) +
              (g_Zpart[(b * 4 + 2) * TT + s] + g_Zpart[(b * 4 + 3) * TT + s]);
    float inv = 1.0f / z;
#pragma unroll
    for (int e = 0; e < NE; ++e)
        g_XZh[((size_t)b * NE + e) * TT + s] =
            __float2half_rn(x[(size_t)gs * NE + e] * inv);
}

// ---------------------------------------------------------------------------
// Kernel 5 (pass B): G = E @ XZ via HMMA (m16n8k16 f16->f32), then out = G @ Wk.
// grid = (T/128 row-tiles, B), block = 128 threads = 4 warps.
// Each warp owns 32 t-rows (2 m16 tiles) x 16 e-cols (2 n8 tiles).
__global__ void __launch_bounds__(128) passB_kernel(const float* __restrict__ Wk,
                                                    float* __restrict__ out) {
    __shared__ __align__(16) __half Ea[128 * 64];   // A tile, XOR-swizzled 16B chunks
    __shared__ __align__(16) __half Bs[NE * 72];    // B tile [e][k], padded stride 72
    __shared__ float Gs[128 * 17];
    __shared__ float wks[NE * HH];

    const int b   = blockIdx.y;
    const int t0  = blockIdx.x * 128;
    const int tid = threadIdx.x;
    const int warp = tid >> 5, lane = tid & 31;

    for (int i = tid; i < NE * HH; i += 128) wks[i] = Wk[i];

    float acc[2][2][4];
#pragma unroll
    for (int mt = 0; mt < 2; ++mt)
#pragma unroll
        for (int nt = 0; nt < 2; ++nt)
#pragma unroll
            for (int r = 0; r < 4; ++r) acc[mt][nt][r] = 0.f;

    const __half* Erow = g_E + ((size_t)(b * TT + t0)) * TT;
    const __half* XZb  = g_XZh + (size_t)b * NE * TT;
    uint32_t EaBase = (uint32_t)__cvta_generic_to_shared(Ea);

    for (int kc = 0; kc < TT; kc += 64) {
        __syncthreads();
        // Stage A: 128 rows x 64 halves (128B/row), swizzled: phys chunk = c ^ (r&7)
        for (int i = tid; i < 128 * 8; i += 128) {
            int r = i >> 3, c = i & 7;
            uint4 v = *(const uint4*)(Erow + (size_t)r * TT + kc + c * 8);
            *(uint4*)((char*)Ea + r * 128 + ((c ^ (r & 7)) * 16)) = v;
        }
        // Stage B: 16 rows x 64 halves (exactly 128 16B chunks)
        {
            int e = tid >> 3, c = tid & 7;
            uint4 v = *(const uint4*)(XZb + (size_t)e * TT + kc + c * 8);
            *(uint4*)(Bs + e * 72 + c * 8) = v;
        }
        __syncthreads();

#pragma unroll
        for (int kt = 0; kt < 4; ++kt) {
            // B fragments (col-major k16 x n8): b0={B[k][n],B[k+1][n]}, b1=k+8
            uint32_t b0[2], b1[2];
#pragma unroll
            for (int nt = 0; nt < 2; ++nt) {
                int n = nt * 8 + (lane >> 2);
                int k = kt * 16 + (lane & 3) * 2;
                b0[nt] = *(const uint32_t*)(Bs + n * 72 + k);
                b1[nt] = *(const uint32_t*)(Bs + n * 72 + k + 8);
            }
#pragma unroll
            for (int mt = 0; mt < 2; ++mt) {
                int row = warp * 32 + mt * 16 + (lane & 15);
                int c   = kt * 2 + (lane >> 4);
                uint32_t addr = EaBase + row * 128 + ((c ^ (row & 7)) * 16);
                uint32_t a0, a1, a2, a3;
                asm volatile(
                    "ldmatrix.sync.aligned.m8n8.x4.shared.b16 {%0,%1,%2,%3}, [%4];"
                    : "=r"(a0), "=r"(a1), "=r"(a2), "=r"(a3) : "r"(addr));
#pragma unroll
                for (int nt = 0; nt < 2; ++nt) {
                    asm volatile(
                        "mma.sync.aligned.m16n8k16.row.col.f32.f16.f16.f32 "
                        "{%0,%1,%2,%3}, {%4,%5,%6,%7}, {%8,%9}, {%0,%1,%2,%3};"
                        : "+f"(acc[mt][nt][0]), "+f"(acc[mt][nt][1]),
                          "+f"(acc[mt][nt][2]), "+f"(acc[mt][nt][3])
                        : "r"(a0), "r"(a1), "r"(a2), "r"(a3),
                          "r"(b0[nt]), "r"(b1[nt]));
                }
            }
        }
    }
    __syncthreads();

    // Spill G fragments to smem: c0=(r,c) c1=(r,c+1) c2=(r+8,c) c3=(r+8,c+1)
#pragma unroll
    for (int mt = 0; mt < 2; ++mt) {
        int r = warp * 32 + mt * 16 + (lane >> 2);
#pragma unroll
        for (int nt = 0; nt < 2; ++nt) {
            int c = nt * 8 + (lane & 3) * 2;
            Gs[r * 17 + c]           = acc[mt][nt][0];
            Gs[r * 17 + c + 1]       = acc[mt][nt][1];
            Gs[(r + 8) * 17 + c]     = acc[mt][nt][2];
            Gs[(r + 8) * 17 + c + 1] = acc[mt][nt][3];
        }
    }
    __syncthreads();

    // Epilogue: out[t, h] = sum_e G[t,e] * Wk[e,h]
    for (int idx = tid; idx < 128 * HH; idx += 128) {
        int r = idx >> 6, h = idx & 63;
        float sum = 0.f;
#pragma unroll
        for (int e = 0; e < NE; ++e) sum += Gs[r * 17 + e] * wks[e * HH + h];
        out[((size_t)(b * TT + t0 + r)) * HH + h] = sum;
    }
}

// ---------------------------------------------------------------------------
extern "C" void kernel_launch(void* const* d_in, const int* in_sizes, int n_in,
                              void* d_out, int out_size) {
    const float* x  = (const float*)d_in[0];   // [B, T, 16]
    const float* Wq = (const float*)d_in[1];   // [16, 64]
    const float* Wk = (const float*)d_in[2];   // [16, 64]
    // d_in[3] = Wv, unused (reference uses Wk for values)
    float* out = (float*)d_out;                // [B, T, 64]

    m_kernel<<<1, 256>>>(Wq, Wk);
    u_kernel<<<(BB * TT) / 128, 128>>>(x);
    passA_kernel<<<dim3(TT / 128, 4, BB), 128>>>(x);
    z_kernel<<<(BB * TT) / 128, 128>>>(x);
    passB_kernel<<<dim3(TT / 128, BB), 128>>>(Wk, out);
}

// round 3
// speedup vs baseline: 2.1428x; 1.3261x over previous
#include <cuda_runtime.h>
#include <cuda_fp16.h>
#include <cstdint>

// Problem constants
#define BB 8
#define TT 4096
#define NE 16
#define HH 64

// Scratch (device globals: allocation-free per harness rules)
__device__ float  g_M[NE * NE];                       // Wq @ Wk^T   (16x16)
__device__ __half g_Uh[BB * TT * NE];                 // fp16 U[b,s,e]
__device__ __half g_Xh[BB * TT * NE];                 // fp16 x[b,t,e]
__device__ float  g_Zpart[BB * 32 * TT];              // per-t-tile column sums of E
__device__ __half g_XZh[BB * NE * TT];                // [b][e][s] = x/Z (fp16, transposed)
__device__ __half g_E[(size_t)BB * TT * TT];          // exp(scores^(-1/16)), 268MB

// ---------------------------------------------------------------------------
// Kernel 1: M = Wq @ Wk^T  (16x16, K=64). One block, 256 threads.
__global__ void m_kernel(const float* __restrict__ Wq, const float* __restrict__ Wk) {
    int e  = threadIdx.x >> 4;
    int e2 = threadIdx.x & 15;
    float s = 0.f;
#pragma unroll
    for (int h = 0; h < HH; ++h)
        s += Wq[e * HH + h] * Wk[e2 * HH + h];
    g_M[e * NE + e2] = s;
}

// ---------------------------------------------------------------------------
// Kernel 2: U[b,s,:] = M @ x[b,s,:] (fp16 out); also x -> fp16.
__global__ void __launch_bounds__(128) u_kernel(const float* __restrict__ x) {
    __shared__ float Ms[NE * NE];
    for (int i = threadIdx.x; i < NE * NE; i += 128) Ms[i] = g_M[i];
    __syncthreads();

    int gs = blockIdx.x * 128 + threadIdx.x;   // 0 .. B*T-1
    float xv[NE];
    const float4* xp = (const float4*)(x + (size_t)gs * NE);
#pragma unroll
    for (int q = 0; q < 4; ++q) {
        float4 v = xp[q];
        xv[q * 4 + 0] = v.x; xv[q * 4 + 1] = v.y;
        xv[q * 4 + 2] = v.z; xv[q * 4 + 3] = v.w;
    }
#pragma unroll
    for (int e = 0; e < NE; ++e)
        g_Xh[(size_t)gs * NE + e] = __float2half_rn(xv[e]);
#pragma unroll
    for (int j = 0; j < NE; ++j) {
        float u = 0.f;
#pragma unroll
        for (int k = 0; k < NE; ++k) u += Ms[j * NE + k] * xv[k];
        g_Uh[(size_t)gs * NE + j] = __float2half_rn(u);
    }
}

// ---------------------------------------------------------------------------
// Kernel 3 (pass A, HMMA): scores tile via mma.m16n8k16 (single k-step),
// then ev = exp(scores^(-1/16)) -> E (fp16), and per-column partial sums.
// grid = (s_tiles=32, t_tiles=32, B), block = 128 (4 warps x 32 t-rows each).
__global__ void __launch_bounds__(128) passA_kernel() {
    __shared__ __align__(16) __half Xs[128 * NE];   // t-rows
    __shared__ __align__(16) __half Us[128 * NE];   // s-rows
    __shared__ float Zs[4][128];

    const int b   = blockIdx.z;
    const int tt0 = blockIdx.y * 128;
    const int ss0 = blockIdx.x * 128;
    const int tid  = threadIdx.x;
    const int warp = tid >> 5, lane = tid & 31;
    const int r  = lane >> 2;          // 0..7
    const int c2 = (lane & 3) * 2;     // 0,2,4,6

    // Stage tiles (4KB each = 256 uint4)
    const uint4* Xsrc = (const uint4*)(g_Xh + ((size_t)b * TT + tt0) * NE);
    const uint4* Usrc = (const uint4*)(g_Uh + ((size_t)b * TT + ss0) * NE);
    ((uint4*)Xs)[tid]       = Xsrc[tid];
    ((uint4*)Xs)[tid + 128] = Xsrc[tid + 128];
    ((uint4*)Us)[tid]       = Usrc[tid];
    ((uint4*)Us)[tid + 128] = Usrc[tid + 128];
    __syncthreads();

    float2 zacc[16];
#pragma unroll
    for (int nt = 0; nt < 16; ++nt) zacc[nt] = make_float2(0.f, 0.f);

    const size_t Erow = ((size_t)b * TT) * TT + ss0;   // + t*TT + col

#pragma unroll
    for (int mt = 0; mt < 2; ++mt) {
        const int row = warp * 32 + mt * 16 + r;       // within 128-tile
        // A fragment (row-major m16k16): direct LDS.32 half2 loads
        uint32_t a0 = *(const uint32_t*)(Xs + row * NE + c2);
        uint32_t a1 = *(const uint32_t*)(Xs + (row + 8) * NE + c2);
        uint32_t a2 = *(const uint32_t*)(Xs + row * NE + c2 + 8);
        uint32_t a3 = *(const uint32_t*)(Xs + (row + 8) * NE + c2 + 8);

#pragma unroll
        for (int nt = 0; nt < 16; ++nt) {
            const int n = nt * 8 + r;
            uint32_t b0 = *(const uint32_t*)(Us + n * NE + c2);
            uint32_t b1 = *(const uint32_t*)(Us + n * NE + c2 + 8);
            float f0 = 0.f, f1 = 0.f, f2 = 0.f, f3 = 0.f;
            asm volatile(
                "mma.sync.aligned.m16n8k16.row.col.f32.f16.f16.f32 "
                "{%0,%1,%2,%3}, {%4,%5,%6,%7}, {%8,%9}, {%0,%1,%2,%3};"
                : "+f"(f0), "+f"(f1), "+f"(f2), "+f"(f3)
                : "r"(a0), "r"(a1), "r"(a2), "r"(a3), "r"(b0), "r"(b1));

            // ev = exp2(1.4427 * exp2(-0.0625 * log2(d)))   (3 MUFU + 2 FMUL)
            float p0 = exp2f(-0.0625f * __log2f(f0));
            float p1 = exp2f(-0.0625f * __log2f(f1));
            float p2 = exp2f(-0.0625f * __log2f(f2));
            float p3 = exp2f(-0.0625f * __log2f(f3));
            float e0 = exp2f(1.44269504f * p0);
            float e1 = exp2f(1.44269504f * p1);
            float e2 = exp2f(1.44269504f * p2);
            float e3 = exp2f(1.44269504f * p3);

            const int trow = tt0 + warp * 32 + mt * 16 + r;
            const int col  = nt * 8 + c2;
            *(__half2*)(g_E + Erow + (size_t)trow * TT + col) =
                __floats2half2_rn(e0, e1);
            *(__half2*)(g_E + Erow + (size_t)(trow + 8) * TT + col) =
                __floats2half2_rn(e2, e3);

            zacc[nt].x += e0 + e2;
            zacc[nt].y += e1 + e3;
        }
    }

    // Reduce column sums across the 8 lanes sharing (lane&3)
#pragma unroll
    for (int nt = 0; nt < 16; ++nt) {
#pragma unroll
        for (int off = 4; off <= 16; off <<= 1) {
            zacc[nt].x += __shfl_xor_sync(0xffffffffu, zacc[nt].x, off);
            zacc[nt].y += __shfl_xor_sync(0xffffffffu, zacc[nt].y, off);
        }
    }
    if (lane < 4) {
#pragma unroll
        for (int nt = 0; nt < 16; ++nt) {
            Zs[warp][nt * 8 + lane * 2]     = zacc[nt].x;
            Zs[warp][nt * 8 + lane * 2 + 1] = zacc[nt].y;
        }
    }
    __syncthreads();
    g_Zpart[((size_t)b * 32 + blockIdx.y) * TT + ss0 + tid] =
        (Zs[0][tid] + Zs[1][tid]) + (Zs[2][tid] + Zs[3][tid]);
}

// ---------------------------------------------------------------------------
// Kernel 4: Z[b,s] = sum of 32 partials (fixed order);
//           XZh[b,e,s] = fp16( x[b,s,e] / Z[b,s] )
__global__ void __launch_bounds__(128) z_kernel(const float* __restrict__ x) {
    int gs = blockIdx.x * 128 + threadIdx.x;   // b*T + s
    int b  = gs >> 12;
    int s  = gs & (TT - 1);
    float z = 0.f;
#pragma unroll
    for (int j = 0; j < 32; ++j)
        z += g_Zpart[((size_t)b * 32 + j) * TT + s];
    float inv = 1.0f / z;
#pragma unroll
    for (int e = 0; e < NE; ++e)
        g_XZh[((size_t)b * NE + e) * TT + s] =
            __float2half_rn(x[(size_t)gs * NE + e] * inv);
}

// ---------------------------------------------------------------------------
// Kernel 5 (pass B): G = E @ XZ via HMMA, then out = G @ Wk.
__global__ void __launch_bounds__(128) passB_kernel(const float* __restrict__ Wk,
                                                    float* __restrict__ out) {
    __shared__ __align__(16) __half Ea[128 * 64];   // A tile, XOR-swizzled 16B chunks
    __shared__ __align__(16) __half Bs[NE * 72];    // B tile [e][k], padded stride 72
    __shared__ float Gs[128 * 17];
    __shared__ float wks[NE * HH];

    const int b   = blockIdx.y;
    const int t0  = blockIdx.x * 128;
    const int tid = threadIdx.x;
    const int warp = tid >> 5, lane = tid & 31;

    for (int i = tid; i < NE * HH; i += 128) wks[i] = Wk[i];

    float acc[2][2][4];
#pragma unroll
    for (int mt = 0; mt < 2; ++mt)
#pragma unroll
        for (int nt = 0; nt < 2; ++nt)
#pragma unroll
            for (int r = 0; r < 4; ++r) acc[mt][nt][r] = 0.f;

    const __half* Erow = g_E + ((size_t)(b * TT + t0)) * TT;
    const __half* XZb  = g_XZh + (size_t)b * NE * TT;
    uint32_t EaBase = (uint32_t)__cvta_generic_to_shared(Ea);

    for (int kc = 0; kc < TT; kc += 64) {
        __syncthreads();
        // Stage A: 128 rows x 64 halves (128B/row), swizzled: phys chunk = c ^ (r&7)
        for (int i = tid; i < 128 * 8; i += 128) {
            int r = i >> 3, c = i & 7;
            uint4 v = *(const uint4*)(Erow + (size_t)r * TT + kc + c * 8);
            *(uint4*)((char*)Ea + r * 128 + ((c ^ (r & 7)) * 16)) = v;
        }
        // Stage B: 16 rows x 64 halves
        {
            int e = tid >> 3, c = tid & 7;
            uint4 v = *(const uint4*)(XZb + (size_t)e * TT + kc + c * 8);
            *(uint4*)(Bs + e * 72 + c * 8) = v;
        }
        __syncthreads();

#pragma unroll
        for (int kt = 0; kt < 4; ++kt) {
            uint32_t b0[2], b1[2];
#pragma unroll
            for (int nt = 0; nt < 2; ++nt) {
                int n = nt * 8 + (lane >> 2);
                int k = kt * 16 + (lane & 3) * 2;
                b0[nt] = *(const uint32_t*)(Bs + n * 72 + k);
                b1[nt] = *(const uint32_t*)(Bs + n * 72 + k + 8);
            }
#pragma unroll
            for (int mt = 0; mt < 2; ++mt) {
                int row = warp * 32 + mt * 16 + (lane & 15);
                int c   = kt * 2 + (lane >> 4);
                uint32_t addr = EaBase + row * 128 + ((c ^ (row & 7)) * 16);
                uint32_t a0, a1, a2, a3;
                asm volatile(
                    "ldmatrix.sync.aligned.m8n8.x4.shared.b16 {%0,%1,%2,%3}, [%4];"
                    : "=r"(a0), "=r"(a1), "=r"(a2), "=r"(a3) : "r"(addr));
#pragma unroll
                for (int nt = 0; nt < 2; ++nt) {
                    asm volatile(
                        "mma.sync.aligned.m16n8k16.row.col.f32.f16.f16.f32 "
                        "{%0,%1,%2,%3}, {%4,%5,%6,%7}, {%8,%9}, {%0,%1,%2,%3};"
                        : "+f"(acc[mt][nt][0]), "+f"(acc[mt][nt][1]),
                          "+f"(acc[mt][nt][2]), "+f"(acc[mt][nt][3])
                        : "r"(a0), "r"(a1), "r"(a2), "r"(a3),
                          "r"(b0[nt]), "r"(b1[nt]));
                }
            }
        }
    }
    __syncthreads();

#pragma unroll
    for (int mt = 0; mt < 2; ++mt) {
        int r = warp * 32 + mt * 16 + (lane >> 2);
#pragma unroll
        for (int nt = 0; nt < 2; ++nt) {
            int c = nt * 8 + (lane & 3) * 2;
            Gs[r * 17 + c]           = acc[mt][nt][0];
            Gs[r * 17 + c + 1]       = acc[mt][nt][1];
            Gs[(r + 8) * 17 + c]     = acc[mt][nt][2];
            Gs[(r + 8) * 17 + c + 1] = acc[mt][nt][3];
        }
    }
    __syncthreads();

    for (int idx = tid; idx < 128 * HH; idx += 128) {
        int r = idx >> 6, h = idx & 63;
        float sum = 0.f;
#pragma unroll
        for (int e = 0; e < NE; ++e) sum += Gs[r * 17 + e] * wks[e * HH + h];
        out[((size_t)(b * TT + t0 + r)) * HH + h] = sum;
    }
}

// ---------------------------------------------------------------------------
extern "C" void kernel_launch(void* const* d_in, const int* in_sizes, int n_in,
                              void* d_out, int out_size) {
    const float* x  = (const float*)d_in[0];   // [B, T, 16]
    const float* Wq = (const float*)d_in[1];   // [16, 64]
    const float* Wk = (const float*)d_in[2];   // [16, 64]
    // d_in[3] = Wv, unused (reference uses Wk for values)
    float* out = (float*)d_out;                // [B, T, 64]

    m_kernel<<<1, 256>>>(Wq, Wk);
    u_kernel<<<(BB * TT) / 128, 128>>>(x);
    passA_kernel<<<dim3(32, 32, BB), 128>>>();
    z_kernel<<<(BB * TT) / 128, 128>>>(x);
    passB_kernel<<<dim3(TT / 128, BB), 128>>>(Wk, out);
}

// round 4
// speedup vs baseline: 3.9048x; 1.8223x over previous
#include <cuda_runtime.h>
#include <cuda_fp16.h>
#include <cstdint>

// Problem constants
#define BB 8
#define TT 4096
#define NE 16
#define HH 64

// Scratch (device globals: allocation-free per harness rules)
__device__ float  g_M[NE * NE];                       // Wq @ Wk^T   (16x16)
__device__ __half g_Uh[BB * TT * NE];                 // fp16 U[b,s,e]
__device__ __half g_Xh[BB * TT * NE];                 // fp16 x[b,t,e]
__device__ float  g_Zpart[BB * 32 * TT];              // per-t-tile column sums of E
__device__ __half g_XZh[BB * NE * TT];                // [b][e][s] = x/Z (fp16, transposed)
__device__ __half g_E[(size_t)BB * TT * TT];          // exp(scores^(-1/16)), 268MB

// ---------------------------------------------------------------------------
// Kernel 1: M = Wq @ Wk^T  (16x16, K=64). One block, 256 threads.
__global__ void m_kernel(const float* __restrict__ Wq, const float* __restrict__ Wk) {
    int e  = threadIdx.x >> 4;
    int e2 = threadIdx.x & 15;
    float s = 0.f;
#pragma unroll
    for (int h = 0; h < HH; ++h)
        s += Wq[e * HH + h] * Wk[e2 * HH + h];
    g_M[e * NE + e2] = s;
}

// ---------------------------------------------------------------------------
// Kernel 2: U[b,s,:] = M @ x[b,s,:] (fp16 out); also x -> fp16.
__global__ void __launch_bounds__(128) u_kernel(const float* __restrict__ x) {
    __shared__ float Ms[NE * NE];
    for (int i = threadIdx.x; i < NE * NE; i += 128) Ms[i] = g_M[i];
    __syncthreads();

    int gs = blockIdx.x * 128 + threadIdx.x;   // 0 .. B*T-1
    float xv[NE];
    const float4* xp = (const float4*)(x + (size_t)gs * NE);
#pragma unroll
    for (int q = 0; q < 4; ++q) {
        float4 v = xp[q];
        xv[q * 4 + 0] = v.x; xv[q * 4 + 1] = v.y;
        xv[q * 4 + 2] = v.z; xv[q * 4 + 3] = v.w;
    }
#pragma unroll
    for (int e = 0; e < NE; ++e)
        g_Xh[(size_t)gs * NE + e] = __float2half_rn(xv[e]);
#pragma unroll
    for (int j = 0; j < NE; ++j) {
        float u = 0.f;
#pragma unroll
        for (int k = 0; k < NE; ++k) u += Ms[j * NE + k] * xv[k];
        g_Uh[(size_t)gs * NE + j] = __float2half_rn(u);
    }
}

// ---------------------------------------------------------------------------
// ev = exp(d^(-1/16)) via degree-5 Taylor in w = log2(d) about w0 = 5.
// Max rel err < 5e-5 for d in [2, 2048]; actual d range ~[9, 170] -> <3e-6.
__device__ __forceinline__ float ev_poly(float d) {
    float w = __log2f(d) - 5.0f;
    float r = fmaf(w, -8.00230e-8f, 2.92128e-6f);
    r = fmaf(r, w, -9.92137e-5f);
    r = fmaf(r, w, 0.00305193f);
    r = fmaf(r, w, -0.0780452f);
    r = fmaf(r, w, 2.2372425f);
    return r;
}

// ---------------------------------------------------------------------------
// Kernel 3 (pass A, HMMA): scores tile via mma.m16n8k16 (single k-step),
// ev via poly, STS into padded smem tile, coalesced STG.64 writeback,
// per-column partial sums in registers.
// grid = (s_tiles=32, t_tiles=32, B), block = 128 (4 warps x 32 t-rows each).
__global__ void __launch_bounds__(128) passA_kernel() {
    __shared__ __align__(16) __half Xs[128 * NE];     // t-rows
    __shared__ __align__(16) __half Us[128 * NE];     // s-rows
    __shared__ __align__(16) __half Et[128 * 136];    // E tile, padded stride 136
    __shared__ float Zs[4][128];

    const int b   = blockIdx.z;
    const int tt0 = blockIdx.y * 128;
    const int ss0 = blockIdx.x * 128;
    const int tid  = threadIdx.x;
    const int warp = tid >> 5, lane = tid & 31;
    const int r  = lane >> 2;          // 0..7
    const int c2 = (lane & 3) * 2;     // 0,2,4,6

    // Stage tiles (4KB each = 256 uint4)
    const uint4* Xsrc = (const uint4*)(g_Xh + ((size_t)b * TT + tt0) * NE);
    const uint4* Usrc = (const uint4*)(g_Uh + ((size_t)b * TT + ss0) * NE);
    ((uint4*)Xs)[tid]       = Xsrc[tid];
    ((uint4*)Xs)[tid + 128] = Xsrc[tid + 128];
    ((uint4*)Us)[tid]       = Usrc[tid];
    ((uint4*)Us)[tid + 128] = Usrc[tid + 128];
    __syncthreads();

    float2 zacc[16];
#pragma unroll
    for (int nt = 0; nt < 16; ++nt) zacc[nt] = make_float2(0.f, 0.f);

#pragma unroll
    for (int mt = 0; mt < 2; ++mt) {
        const int row = warp * 32 + mt * 16 + r;       // within 128-tile
        // A fragment (row-major m16k16): direct LDS.32 half2 loads
        uint32_t a0 = *(const uint32_t*)(Xs + row * NE + c2);
        uint32_t a1 = *(const uint32_t*)(Xs + (row + 8) * NE + c2);
        uint32_t a2 = *(const uint32_t*)(Xs + row * NE + c2 + 8);
        uint32_t a3 = *(const uint32_t*)(Xs + (row + 8) * NE + c2 + 8);

#pragma unroll
        for (int nt = 0; nt < 16; ++nt) {
            const int n = nt * 8 + r;
            uint32_t b0 = *(const uint32_t*)(Us + n * NE + c2);
            uint32_t b1 = *(const uint32_t*)(Us + n * NE + c2 + 8);
            float f0 = 0.f, f1 = 0.f, f2 = 0.f, f3 = 0.f;
            asm volatile(
                "mma.sync.aligned.m16n8k16.row.col.f32.f16.f16.f32 "
                "{%0,%1,%2,%3}, {%4,%5,%6,%7}, {%8,%9}, {%0,%1,%2,%3};"
                : "+f"(f0), "+f"(f1), "+f"(f2), "+f"(f3)
                : "r"(a0), "r"(a1), "r"(a2), "r"(a3), "r"(b0), "r"(b1));

            float e0 = ev_poly(f0);
            float e1 = ev_poly(f1);
            float e2 = ev_poly(f2);
            float e3 = ev_poly(f3);

            const int col = nt * 8 + c2;
            *(__half2*)(Et + row * 136 + col)       = __floats2half2_rn(e0, e1);
            *(__half2*)(Et + (row + 8) * 136 + col) = __floats2half2_rn(e2, e3);

            zacc[nt].x += e0 + e2;
            zacc[nt].y += e1 + e3;
        }
    }
    __syncthreads();

    // Coalesced writeback: each warp handles 32 rows; 32 lanes x 8B = 256B/row
    {
        const size_t Ebase = ((size_t)b * TT + tt0) * TT + ss0;
#pragma unroll 4
        for (int i = 0; i < 32; ++i) {
            int row = warp * 32 + i;
            *(uint2*)(g_E + Ebase + (size_t)row * TT + lane * 4) =
                *(const uint2*)(Et + row * 136 + lane * 4);
        }
    }

    // Reduce column sums across the 8 lanes sharing (lane&3)
#pragma unroll
    for (int nt = 0; nt < 16; ++nt) {
#pragma unroll
        for (int off = 4; off <= 16; off <<= 1) {
            zacc[nt].x += __shfl_xor_sync(0xffffffffu, zacc[nt].x, off);
            zacc[nt].y += __shfl_xor_sync(0xffffffffu, zacc[nt].y, off);
        }
    }
    if (lane < 4) {
#pragma unroll
        for (int nt = 0; nt < 16; ++nt) {
            Zs[warp][nt * 8 + lane * 2]     = zacc[nt].x;
            Zs[warp][nt * 8 + lane * 2 + 1] = zacc[nt].y;
        }
    }
    __syncthreads();
    g_Zpart[((size_t)b * 32 + blockIdx.y) * TT + ss0 + tid] =
        (Zs[0][tid] + Zs[1][tid]) + (Zs[2][tid] + Zs[3][tid]);
}

// ---------------------------------------------------------------------------
// Kernel 4: Z[b,s] = sum of 32 partials (fixed order);
//           XZh[b,e,s] = fp16( x[b,s,e] / Z[b,s] )
__global__ void __launch_bounds__(128) z_kernel(const float* __restrict__ x) {
    int gs = blockIdx.x * 128 + threadIdx.x;   // b*T + s
    int b  = gs >> 12;
    int s  = gs & (TT - 1);
    float z = 0.f;
#pragma unroll
    for (int j = 0; j < 32; ++j)
        z += g_Zpart[((size_t)b * 32 + j) * TT + s];
    float inv = 1.0f / z;
#pragma unroll
    for (int e = 0; e < NE; ++e)
        g_XZh[((size_t)b * NE + e) * TT + s] =
            __float2half_rn(x[(size_t)gs * NE + e] * inv);
}

// ---------------------------------------------------------------------------
// cp.async helpers
__device__ __forceinline__ void cp16(uint32_t dst, const void* src) {
    asm volatile("cp.async.cg.shared.global [%0], [%1], 16;\n"
                 :: "r"(dst), "l"(src));
}
__device__ __forceinline__ void cp_commit() {
    asm volatile("cp.async.commit_group;\n");
}
__device__ __forceinline__ void cp_wait1() {
    asm volatile("cp.async.wait_group 1;\n" ::: "memory");
}
__device__ __forceinline__ void cp_wait0() {
    asm volatile("cp.async.wait_group 0;\n" ::: "memory");
}

// ---------------------------------------------------------------------------
// Kernel 5 (pass B): G = E @ XZ via HMMA with double-buffered cp.async
// staging, then out = G @ Wk.
__global__ void __launch_bounds__(128) passB_kernel(const float* __restrict__ Wk,
                                                    float* __restrict__ out) {
    __shared__ __align__(16) __half Ea[2][128 * 64];  // A tiles, XOR-swizzled
    __shared__ __align__(16) __half Bs[2][NE * 72];   // B tiles [e][k], stride 72
    __shared__ float Gs[128 * 17];
    __shared__ float wks[NE * HH];

    const int b   = blockIdx.y;
    const int t0  = blockIdx.x * 128;
    const int tid = threadIdx.x;
    const int warp = tid >> 5, lane = tid & 31;

    for (int i = tid; i < NE * HH; i += 128) wks[i] = Wk[i];

    float acc[2][2][4];
#pragma unroll
    for (int mt = 0; mt < 2; ++mt)
#pragma unroll
        for (int nt = 0; nt < 2; ++nt)
#pragma unroll
            for (int r = 0; r < 4; ++r) acc[mt][nt][r] = 0.f;

    const __half* Erow = g_E + ((size_t)(b * TT + t0)) * TT;
    const __half* XZb  = g_XZh + (size_t)b * NE * TT;
    const uint32_t EaBase = (uint32_t)__cvta_generic_to_shared(&Ea[0][0]);
    const uint32_t BsBase = (uint32_t)__cvta_generic_to_shared(&Bs[0][0]);

    // Stage chunk (64 k-cols) into buffer buf via cp.async
    auto stage = [&](int buf, int kc) {
        // A: 128 rows x 8 chunks of 16B, swizzled phys chunk = c ^ (r&7)
#pragma unroll
        for (int q = 0; q < 8; ++q) {
            int i = q * 128 + tid;
            int r = i >> 3, c = i & 7;
            cp16(EaBase + buf * 16384 + r * 128 + ((c ^ (r & 7)) * 16),
                 Erow + (size_t)r * TT + kc + c * 8);
        }
        // B: 16 rows x 8 chunks of 16B
        {
            int e = tid >> 3, c = tid & 7;
            cp16(BsBase + buf * (NE * 72 * 2) + (e * 72 + c * 8) * 2,
                 XZb + (size_t)e * TT + kc + c * 8);
        }
    };

    stage(0, 0);
    cp_commit();

    for (int kc = 0; kc < TT; kc += 64) {
        const int buf = (kc >> 6) & 1;
        if (kc + 64 < TT) {
            stage(buf ^ 1, kc + 64);
            cp_commit();
            cp_wait1();
        } else {
            cp_wait0();
        }
        __syncthreads();

        const __half* Bb = Bs[buf];
        const uint32_t EaB = EaBase + buf * 16384;
#pragma unroll
        for (int kt = 0; kt < 4; ++kt) {
            uint32_t b0[2], b1[2];
#pragma unroll
            for (int nt = 0; nt < 2; ++nt) {
                int n = nt * 8 + (lane >> 2);
                int k = kt * 16 + (lane & 3) * 2;
                b0[nt] = *(const uint32_t*)(Bb + n * 72 + k);
                b1[nt] = *(const uint32_t*)(Bb + n * 72 + k + 8);
            }
#pragma unroll
            for (int mt = 0; mt < 2; ++mt) {
                int row = warp * 32 + mt * 16 + (lane & 15);
                int c   = kt * 2 + (lane >> 4);
                uint32_t addr = EaB + row * 128 + ((c ^ (row & 7)) * 16);
                uint32_t a0, a1, a2, a3;
                asm volatile(
                    "ldmatrix.sync.aligned.m8n8.x4.shared.b16 {%0,%1,%2,%3}, [%4];"
                    : "=r"(a0), "=r"(a1), "=r"(a2), "=r"(a3) : "r"(addr));
#pragma unroll
                for (int nt = 0; nt < 2; ++nt) {
                    asm volatile(
                        "mma.sync.aligned.m16n8k16.row.col.f32.f16.f16.f32 "
                        "{%0,%1,%2,%3}, {%4,%5,%6,%7}, {%8,%9}, {%0,%1,%2,%3};"
                        : "+f"(acc[mt][nt][0]), "+f"(acc[mt][nt][1]),
                          "+f"(acc[mt][nt][2]), "+f"(acc[mt][nt][3])
                        : "r"(a0), "r"(a1), "r"(a2), "r"(a3),
                          "r"(b0[nt]), "r"(b1[nt]));
                }
            }
        }
        __syncthreads();
    }

#pragma unroll
    for (int mt = 0; mt < 2; ++mt) {
        int r = warp * 32 + mt * 16 + (lane >> 2);
#pragma unroll
        for (int nt = 0; nt < 2; ++nt) {
            int c = nt * 8 + (lane & 3) * 2;
            Gs[r * 17 + c]           = acc[mt][nt][0];
            Gs[r * 17 + c + 1]       = acc[mt][nt][1];
            Gs[(r + 8) * 17 + c]     = acc[mt][nt][2];
            Gs[(r + 8) * 17 + c + 1] = acc[mt][nt][3];
        }
    }
    __syncthreads();

    for (int idx = tid; idx < 128 * HH; idx += 128) {
        int r = idx >> 6, h = idx & 63;
        float sum = 0.f;
#pragma unroll
        for (int e = 0; e < NE; ++e) sum += Gs[r * 17 + e] * wks[e * HH + h];
        out[((size_t)(b * TT + t0 + r)) * HH + h] = sum;
    }
}

// ---------------------------------------------------------------------------
extern "C" void kernel_launch(void* const* d_in, const int* in_sizes, int n_in,
                              void* d_out, int out_size) {
    const float* x  = (const float*)d_in[0];   // [B, T, 16]
    const float* Wq = (const float*)d_in[1];   // [16, 64]
    const float* Wk = (const float*)d_in[2];   // [16, 64]
    // d_in[3] = Wv, unused (reference uses Wk for values)
    float* out = (float*)d_out;                // [B, T, 64]

    m_kernel<<<1, 256>>>(Wq, Wk);
    u_kernel<<<(BB * TT) / 128, 128>>>(x);
    passA_kernel<<<dim3(32, 32, BB), 128>>>();
    z_kernel<<<(BB * TT) / 128, 128>>>(x);
    passB_kernel<<<dim3(TT / 128, BB), 128>>>(Wk, out);
}

// round 6
// speedup vs baseline: 4.7184x; 1.2084x over previous
#include <cuda_runtime.h>
#include <cuda_fp16.h>
#include <cstdint>

// Problem constants
#define BB 8
#define TT 4096
#define NE 16
#define HH 64

// Scratch (device globals: allocation-free per harness rules). No g_E anymore.
__device__ float  g_M[NE * NE];                       // Wq @ Wk^T   (16x16)
__device__ __half g_Uh[BB * TT * NE];                 // fp16 U[b,s,e]
__device__ __half g_Xh[BB * TT * NE];                 // fp16 x[b,t,e]
__device__ float  g_Zpart[BB * 32 * TT];              // per-t-tile column sums of E
__device__ __half g_XZh[BB * NE * TT];                // [b][e][s] = x/Z (fp16, transposed)

// ---------------------------------------------------------------------------
// f32x2 packed helpers (FFMA2: PTX-only, ptxas won't auto-fuse)
__device__ __forceinline__ uint64_t pk2(float a, float b) {
    uint64_t r; asm("mov.b64 %0, {%1, %2};" : "=l"(r) : "f"(a), "f"(b)); return r;
}
__device__ __forceinline__ void up2(uint64_t v, float& a, float& b) {
    asm("mov.b64 {%0, %1}, %2;" : "=f"(a), "=f"(b) : "l"(v));
}
__device__ __forceinline__ uint64_t fma2_(uint64_t a, uint64_t b, uint64_t c) {
    uint64_t r; asm("fma.rn.f32x2 %0, %1, %2, %3;" : "=l"(r) : "l"(a), "l"(b), "l"(c)); return r;
}
__device__ __forceinline__ uint64_t add2_(uint64_t a, uint64_t b) {
    uint64_t r; asm("add.rn.f32x2 %0, %1, %2;" : "=l"(r) : "l"(a), "l"(b)); return r;
}

// ev = exp(d^(-1/16)) via degree-5 Taylor in w = log2(d) - 5; packed pair.
// Max rel err < 5e-5 for d in [2, 2048]; actual d ~[9, 170] -> <3e-6.
__device__ __forceinline__ uint64_t ev2(float d0, float d1) {
    uint64_t w = add2_(pk2(__log2f(d0), __log2f(d1)), pk2(-5.0f, -5.0f));
    uint64_t r = fma2_(w, pk2(-8.00230e-8f, -8.00230e-8f), pk2(2.92128e-6f, 2.92128e-6f));
    r = fma2_(r, w, pk2(-9.92137e-5f, -9.92137e-5f));
    r = fma2_(r, w, pk2(0.00305193f, 0.00305193f));
    r = fma2_(r, w, pk2(-0.0780452f, -0.0780452f));
    r = fma2_(r, w, pk2(2.2372425f, 2.2372425f));
    return r;
}
__device__ __forceinline__ uint32_t ev2h(float d0, float d1) {
    float lo, hi; up2(ev2(d0, d1), lo, hi);
    __half2 h = __floats2half2_rn(lo, hi);
    return *(uint32_t*)&h;
}

// cp.async helpers
__device__ __forceinline__ void cp16(uint32_t dst, const void* src) {
    asm volatile("cp.async.cg.shared.global [%0], [%1], 16;\n" :: "r"(dst), "l"(src));
}
__device__ __forceinline__ void cp_commit() { asm volatile("cp.async.commit_group;\n"); }
__device__ __forceinline__ void cp_wait1()  { asm volatile("cp.async.wait_group 1;\n" ::: "memory"); }
__device__ __forceinline__ void cp_wait0()  { asm volatile("cp.async.wait_group 0;\n" ::: "memory"); }

// ---------------------------------------------------------------------------
// Kernel 1: M = Wq @ Wk^T  (16x16, K=64). One block, 256 threads.
__global__ void m_kernel(const float* __restrict__ Wq, const float* __restrict__ Wk) {
    int e  = threadIdx.x >> 4;
    int e2 = threadIdx.x & 15;
    float s = 0.f;
#pragma unroll
    for (int h = 0; h < HH; ++h)
        s += Wq[e * HH + h] * Wk[e2 * HH + h];
    g_M[e * NE + e2] = s;
}

// ---------------------------------------------------------------------------
// Kernel 2: U[b,s,:] = M @ x[b,s,:] (fp16 out); also x -> fp16.
__global__ void __launch_bounds__(128) u_kernel(const float* __restrict__ x) {
    __shared__ float Ms[NE * NE];
    for (int i = threadIdx.x; i < NE * NE; i += 128) Ms[i] = g_M[i];
    __syncthreads();

    int gs = blockIdx.x * 128 + threadIdx.x;   // 0 .. B*T-1
    float xv[NE];
    const float4* xp = (const float4*)(x + (size_t)gs * NE);
#pragma unroll
    for (int q = 0; q < 4; ++q) {
        float4 v = xp[q];
        xv[q * 4 + 0] = v.x; xv[q * 4 + 1] = v.y;
        xv[q * 4 + 2] = v.z; xv[q * 4 + 3] = v.w;
    }
#pragma unroll
    for (int e = 0; e < NE; ++e)
        g_Xh[(size_t)gs * NE + e] = __float2half_rn(xv[e]);
#pragma unroll
    for (int j = 0; j < NE; ++j) {
        float u = 0.f;
#pragma unroll
        for (int k = 0; k < NE; ++k) u += Ms[j * NE + k] * xv[k];
        g_Uh[(size_t)gs * NE + j] = __float2half_rn(u);
    }
}

// ---------------------------------------------------------------------------
// Kernel 3 (pass A'): column sums of E only. No E store.
// grid = (s_tiles=32, t_tiles=32, B), block = 128 (4 warps x 32 t-rows each).
__global__ void __launch_bounds__(128) passA_kernel() {
    __shared__ __align__(16) __half Xs[128 * NE];     // t-rows
    __shared__ __align__(16) __half Us[128 * NE];     // s-rows
    __shared__ float Zs[4][128];

    const int b   = blockIdx.z;
    const int tt0 = blockIdx.y * 128;
    const int ss0 = blockIdx.x * 128;
    const int tid  = threadIdx.x;
    const int warp = tid >> 5, lane = tid & 31;
    const int r  = lane >> 2;          // 0..7
    const int c2 = (lane & 3) * 2;     // 0,2,4,6

    const uint4* Xsrc = (const uint4*)(g_Xh + ((size_t)b * TT + tt0) * NE);
    const uint4* Usrc = (const uint4*)(g_Uh + ((size_t)b * TT + ss0) * NE);
    ((uint4*)Xs)[tid]       = Xsrc[tid];
    ((uint4*)Xs)[tid + 128] = Xsrc[tid + 128];
    ((uint4*)Us)[tid]       = Usrc[tid];
    ((uint4*)Us)[tid + 128] = Usrc[tid + 128];
    __syncthreads();

    uint64_t zacc[16];
#pragma unroll
    for (int nt = 0; nt < 16; ++nt) zacc[nt] = pk2(0.f, 0.f);

#pragma unroll
    for (int mt = 0; mt < 2; ++mt) {
        const int row = warp * 32 + mt * 16 + r;
        uint32_t a0 = *(const uint32_t*)(Xs + row * NE + c2);
        uint32_t a1 = *(const uint32_t*)(Xs + (row + 8) * NE + c2);
        uint32_t a2 = *(const uint32_t*)(Xs + row * NE + c2 + 8);
        uint32_t a3 = *(const uint32_t*)(Xs + (row + 8) * NE + c2 + 8);

#pragma unroll
        for (int nt = 0; nt < 16; ++nt) {
            const int n = nt * 8 + r;
            uint32_t b0 = *(const uint32_t*)(Us + n * NE + c2);
            uint32_t b1 = *(const uint32_t*)(Us + n * NE + c2 + 8);
            float f0 = 0.f, f1 = 0.f, f2 = 0.f, f3 = 0.f;
            asm volatile(
                "mma.sync.aligned.m16n8k16.row.col.f32.f16.f16.f32 "
                "{%0,%1,%2,%3}, {%4,%5,%6,%7}, {%8,%9}, {%0,%1,%2,%3};"
                : "+f"(f0), "+f"(f1), "+f"(f2), "+f"(f3)
                : "r"(a0), "r"(a1), "r"(a2), "r"(a3), "r"(b0), "r"(b1));
            zacc[nt] = add2_(zacc[nt], add2_(ev2(f0, f1), ev2(f2, f3)));
        }
    }

    // Reduce column sums across the 8 lanes sharing (lane&3)
#pragma unroll
    for (int nt = 0; nt < 16; ++nt) {
        float zx, zy; up2(zacc[nt], zx, zy);
#pragma unroll
        for (int off = 4; off <= 16; off <<= 1) {
            zx += __shfl_xor_sync(0xffffffffu, zx, off);
            zy += __shfl_xor_sync(0xffffffffu, zy, off);
        }
        if (lane < 4) {
            Zs[warp][nt * 8 + lane * 2]     = zx;
            Zs[warp][nt * 8 + lane * 2 + 1] = zy;
        }
    }
    __syncthreads();
    g_Zpart[((size_t)b * 32 + blockIdx.y) * TT + ss0 + tid] =
        (Zs[0][tid] + Zs[1][tid]) + (Zs[2][tid] + Zs[3][tid]);
}

// ---------------------------------------------------------------------------
// Kernel 4: Z[b,s] = sum of 32 partials (fixed order);
//           XZh[b,e,s] = fp16( x[b,s,e] / Z[b,s] )
__global__ void __launch_bounds__(128) z_kernel(const float* __restrict__ x) {
    int gs = blockIdx.x * 128 + threadIdx.x;   // b*T + s
    int b  = gs >> 12;
    int s  = gs & (TT - 1);
    float z = 0.f;
#pragma unroll
    for (int j = 0; j < 32; ++j)
        z += g_Zpart[((size_t)b * 32 + j) * TT + s];
    float inv = 1.0f / z;
#pragma unroll
    for (int e = 0; e < NE; ++e)
        g_XZh[((size_t)b * NE + e) * TT + s] =
            __float2half_rn(x[(size_t)gs * NE + e] * inv);
}

// ---------------------------------------------------------------------------
// Kernel 5 (pass B'): recompute E tile in registers (mma1 -> poly -> half2)
// and feed directly as A of mma2 (fragment layouts match). G accumulates in
// registers over all s; epilogue out = G @ Wk.
// grid = (32 t-tiles, B), block = 128 = 4 warps x 32 t-rows.
__global__ void __launch_bounds__(128) passB_kernel(const float* __restrict__ Wk,
                                                    float* __restrict__ out) {
    __shared__ __align__(16) __half Xs[128 * NE];
    __shared__ __align__(16) __half Us[2][128 * NE];      // s-chunk U tiles
    __shared__ __align__(16) __half XZs[2][NE * 136];     // [e][s] tiles, stride 136
    __shared__ float Gs[128 * 17];
    __shared__ float wks[NE * HH];

    const int b   = blockIdx.y;
    const int t0  = blockIdx.x * 128;
    const int tid = threadIdx.x;
    const int warp = tid >> 5, lane = tid & 31;
    const int r  = lane >> 2;
    const int c2 = (lane & 3) * 2;

    for (int i = tid; i < NE * HH; i += 128) wks[i] = Wk[i];
    {
        const uint4* Xsrc = (const uint4*)(g_Xh + ((size_t)b * TT + t0) * NE);
        ((uint4*)Xs)[tid]       = Xsrc[tid];
        ((uint4*)Xs)[tid + 128] = Xsrc[tid + 128];
    }
    __syncthreads();

    // A fragments of mma1 (X rows), loaded once
    uint32_t xa[2][4];
#pragma unroll
    for (int mt = 0; mt < 2; ++mt) {
        int row = warp * 32 + mt * 16 + r;
        xa[mt][0] = *(const uint32_t*)(Xs + row * NE + c2);
        xa[mt][1] = *(const uint32_t*)(Xs + (row + 8) * NE + c2);
        xa[mt][2] = *(const uint32_t*)(Xs + row * NE + c2 + 8);
        xa[mt][3] = *(const uint32_t*)(Xs + (row + 8) * NE + c2 + 8);
    }

    float acc[2][2][4];
#pragma unroll
    for (int mt = 0; mt < 2; ++mt)
#pragma unroll
        for (int ne = 0; ne < 2; ++ne)
#pragma unroll
            for (int q = 0; q < 4; ++q) acc[mt][ne][q] = 0.f;

    const __half* Ub  = g_Uh + (size_t)b * TT * NE;
    const __half* XZb = g_XZh + (size_t)b * NE * TT;
    const uint32_t UsB  = (uint32_t)__cvta_generic_to_shared(&Us[0][0]);
    const uint32_t XZB  = (uint32_t)__cvta_generic_to_shared(&XZs[0][0]);

    auto stage = [&](int buf, int sc) {
        // U: 128 rows x 32B = 256 x 16B chunks
#pragma unroll
        for (int q = 0; q < 2; ++q) {
            int i = q * 128 + tid;
            int row = i >> 1, c = i & 1;
            cp16(UsB + buf * 4096 + row * 32 + c * 16,
                 Ub + (size_t)(sc + row) * NE + c * 8);
        }
        // XZ: 16 e-rows x 128 halves = 16 rows x 16 chunks of 16B = 256 chunks
        // dst row stride 272B (= 17*16, keeps 16B alignment)
#pragma unroll
        for (int q = 0; q < 2; ++q) {
            int j = q * 128 + tid;
            int e = j >> 4, c = j & 15;
            cp16(XZB + buf * 4352 + e * 272 + c * 16,
                 XZb + (size_t)e * TT + sc + c * 8);
        }
    };

    stage(0, 0);
    cp_commit();

    for (int sc = 0; sc < TT; sc += 128) {
        const int buf = (sc >> 7) & 1;
        if (sc + 128 < TT) {
            stage(buf ^ 1, sc + 128);
            cp_commit();
            cp_wait1();
        } else {
            cp_wait0();
        }
        __syncthreads();

        const __half* Ubuf  = Us[buf];
        const __half* Zbuf  = XZs[buf];

#pragma unroll
        for (int ss = 0; ss < 8; ++ss) {
            const int s0 = ss * 16;
            // mma1 B fragments (U, col-major k=e): shared across mt
            uint32_t ub0[2], ub1[2];
#pragma unroll
            for (int nt = 0; nt < 2; ++nt) {
                int n = s0 + nt * 8 + r;
                ub0[nt] = *(const uint32_t*)(Ubuf + n * NE + c2);
                ub1[nt] = *(const uint32_t*)(Ubuf + n * NE + c2 + 8);
            }
            // mma2 B fragments (XZ, col-major k=s, n=e)
            uint32_t vb0[2], vb1[2];
#pragma unroll
            for (int ne = 0; ne < 2; ++ne) {
                int n = ne * 8 + r;
                vb0[ne] = *(const uint32_t*)(Zbuf + n * 136 + s0 + c2);
                vb1[ne] = *(const uint32_t*)(Zbuf + n * 136 + s0 + c2 + 8);
            }

#pragma unroll
            for (int mt = 0; mt < 2; ++mt) {
                float f[2][4];
#pragma unroll
                for (int nt = 0; nt < 2; ++nt) {
                    f[nt][0] = 0.f; f[nt][1] = 0.f; f[nt][2] = 0.f; f[nt][3] = 0.f;
                    asm volatile(
                        "mma.sync.aligned.m16n8k16.row.col.f32.f16.f16.f32 "
                        "{%0,%1,%2,%3}, {%4,%5,%6,%7}, {%8,%9}, {%0,%1,%2,%3};"
                        : "+f"(f[nt][0]), "+f"(f[nt][1]), "+f"(f[nt][2]), "+f"(f[nt][3])
                        : "r"(xa[mt][0]), "r"(xa[mt][1]), "r"(xa[mt][2]), "r"(xa[mt][3]),
                          "r"(ub0[nt]), "r"(ub1[nt]));
                }
                // E fragment = A fragment of mma2 (layout identity)
                uint32_t ea0 = ev2h(f[0][0], f[0][1]);
                uint32_t ea1 = ev2h(f[0][2], f[0][3]);
                uint32_t ea2 = ev2h(f[1][0], f[1][1]);
                uint32_t ea3 = ev2h(f[1][2], f[1][3]);
#pragma unroll
                for (int ne = 0; ne < 2; ++ne) {
                    asm volatile(
                        "mma.sync.aligned.m16n8k16.row.col.f32.f16.f16.f32 "
                        "{%0,%1,%2,%3}, {%4,%5,%6,%7}, {%8,%9}, {%0,%1,%2,%3};"
                        : "+f"(acc[mt][ne][0]), "+f"(acc[mt][ne][1]),
                          "+f"(acc[mt][ne][2]), "+f"(acc[mt][ne][3])
                        : "r"(ea0), "r"(ea1), "r"(ea2), "r"(ea3),
                          "r"(vb0[ne]), "r"(vb1[ne]));
                }
            }
        }
        __syncthreads();
    }

    // Spill G fragments to smem
#pragma unroll
    for (int mt = 0; mt < 2; ++mt) {
        int rr = warp * 32 + mt * 16 + (lane >> 2);
#pragma unroll
        for (int ne = 0; ne < 2; ++ne) {
            int c = ne * 8 + (lane & 3) * 2;
            Gs[rr * 17 + c]           = acc[mt][ne][0];
            Gs[rr * 17 + c + 1]       = acc[mt][ne][1];
            Gs[(rr + 8) * 17 + c]     = acc[mt][ne][2];
            Gs[(rr + 8) * 17 + c + 1] = acc[mt][ne][3];
        }
    }
    __syncthreads();

    // Epilogue: out[t, h] = sum_e G[t,e] * Wk[e,h]
    for (int idx = tid; idx < 128 * HH; idx += 128) {
        int rr = idx >> 6, h = idx & 63;
        float sum = 0.f;
#pragma unroll
        for (int e = 0; e < NE; ++e) sum += Gs[rr * 17 + e] * wks[e * HH + h];
        out[((size_t)(b * TT + t0 + rr)) * HH + h] = sum;
    }
}

// ---------------------------------------------------------------------------
extern "C" void kernel_launch(void* const* d_in, const int* in_sizes, int n_in,
                              void* d_out, int out_size) {
    const float* x  = (const float*)d_in[0];   // [B, T, 16]
    const float* Wq = (const float*)d_in[1];   // [16, 64]
    const float* Wk = (const float*)d_in[2];   // [16, 64]
    // d_in[3] = Wv, unused (reference uses Wk for values)
    float* out = (float*)d_out;                // [B, T, 64]

    m_kernel<<<1, 256>>>(Wq, Wk);
    u_kernel<<<(BB * TT) / 128, 128>>>(x);
    passA_kernel<<<dim3(32, 32, BB), 128>>>();
    z_kernel<<<(BB * TT) / 128, 128>>>(x);
    passB_kernel<<<dim3(TT / 128, BB), 128>>>(Wk, out);
}

// round 7
// speedup vs baseline: 5.4526x; 1.1556x over previous
#include <cuda_runtime.h>
#include <cuda_fp16.h>
#include <cstdint>

// Problem constants
#define BB 8
#define TT 4096
#define NE 16
#define HH 64

// Scratch (device globals: allocation-free per harness rules)
__device__ __half g_Uh[BB * TT * NE];                 // fp16 U[b,s,e]
__device__ __half g_Xh[BB * TT * NE];                 // fp16 x[b,t,e]
__device__ float  g_Zpart[BB * 32 * TT];              // per-t-tile column sums of E
__device__ __half g_XZh[BB * NE * TT];                // [b][e][s] = x/Z (fp16, transposed)
__device__ float  g_Gpart[BB * 2 * 64 * 64 * NE];     // partial G tiles (s-split)

// ---------------------------------------------------------------------------
// f32x2 packed helpers (FFMA2: PTX-only, ptxas won't auto-fuse)
__device__ __forceinline__ uint64_t pk2(float a, float b) {
    uint64_t r; asm("mov.b64 %0, {%1, %2};" : "=l"(r) : "f"(a), "f"(b)); return r;
}
__device__ __forceinline__ void up2(uint64_t v, float& a, float& b) {
    asm("mov.b64 {%0, %1}, %2;" : "=f"(a), "=f"(b) : "l"(v));
}
__device__ __forceinline__ uint64_t fma2_(uint64_t a, uint64_t b, uint64_t c) {
    uint64_t r; asm("fma.rn.f32x2 %0, %1, %2, %3;" : "=l"(r) : "l"(a), "l"(b), "l"(c)); return r;
}
__device__ __forceinline__ uint64_t add2_(uint64_t a, uint64_t b) {
    uint64_t r; asm("add.rn.f32x2 %0, %1, %2;" : "=l"(r) : "l"(a), "l"(b)); return r;
}

// ev = exp(d^(-1/16)) via degree-4 poly in w = log2(d), monomial form.
// Validated against exact at w in [2, 8.5]: rel err <= 4e-5 (d ~ [4, 362];
// actual d range ~[9, 170] -> ~1e-5).
__device__ __forceinline__ uint64_t ev2(float d0, float d1) {
    uint64_t w = pk2(__log2f(d0), __log2f(d1));
    uint64_t r = fma2_(w, pk2(2.9219e-6f, 2.9219e-6f), pk2(-1.57661e-4f, -1.57661e-4f));
    r = fma2_(r, w, pk2(0.00497842f, 0.00497842f));
    r = fma2_(r, w, pk2(-0.117466f, -0.117466f));
    r = fma2_(r, w, pk2(2.717994f, 2.717994f));
    return r;
}
__device__ __forceinline__ uint32_t ev2h(float d0, float d1) {
    float lo, hi; up2(ev2(d0, d1), lo, hi);
    __half2 h = __floats2half2_rn(lo, hi);
    return *(uint32_t*)&h;
}

// cp.async helpers
__device__ __forceinline__ void cp16(uint32_t dst, const void* src) {
    asm volatile("cp.async.cg.shared.global [%0], [%1], 16;\n" :: "r"(dst), "l"(src));
}
__device__ __forceinline__ void cp_commit() { asm volatile("cp.async.commit_group;\n"); }
__device__ __forceinline__ void cp_wait1()  { asm volatile("cp.async.wait_group 1;\n" ::: "memory"); }
__device__ __forceinline__ void cp_wait0()  { asm volatile("cp.async.wait_group 0;\n" ::: "memory"); }

// ---------------------------------------------------------------------------
// Kernel 1 (merged m+u): M = Wq@Wk^T in smem, then U[b,s,:] = M @ x[b,s,:]
// (fp16 out); also x -> fp16.
__global__ void __launch_bounds__(128) u_kernel(const float* __restrict__ x,
                                                const float* __restrict__ Wq,
                                                const float* __restrict__ Wk) {
    __shared__ float Ms[NE * NE];
    // Each thread computes 2 entries of M (16x16, K=64)
#pragma unroll
    for (int j = 0; j < 2; ++j) {
        int idx = threadIdx.x * 2 + j;
        int e = idx >> 4, e2 = idx & 15;
        float s = 0.f;
#pragma unroll
        for (int h = 0; h < HH; ++h)
            s += Wq[e * HH + h] * Wk[e2 * HH + h];
        Ms[idx] = s;
    }
    __syncthreads();

    int gs = blockIdx.x * 128 + threadIdx.x;   // 0 .. B*T-1
    float xv[NE];
    const float4* xp = (const float4*)(x + (size_t)gs * NE);
#pragma unroll
    for (int q = 0; q < 4; ++q) {
        float4 v = xp[q];
        xv[q * 4 + 0] = v.x; xv[q * 4 + 1] = v.y;
        xv[q * 4 + 2] = v.z; xv[q * 4 + 3] = v.w;
    }
#pragma unroll
    for (int e = 0; e < NE; ++e)
        g_Xh[(size_t)gs * NE + e] = __float2half_rn(xv[e]);
#pragma unroll
    for (int j = 0; j < NE; ++j) {
        float u = 0.f;
#pragma unroll
        for (int k = 0; k < NE; ++k) u += Ms[j * NE + k] * xv[k];
        g_Uh[(size_t)gs * NE + j] = __float2half_rn(u);
    }
}

// ---------------------------------------------------------------------------
// Kernel 2 (pass A'): column sums of E only. No E store.
// grid = (s_tiles=32, t_tiles=32, B), block = 128 (4 warps x 32 t-rows each).
__global__ void __launch_bounds__(128) passA_kernel() {
    __shared__ __align__(16) __half Xs[128 * NE];     // t-rows
    __shared__ __align__(16) __half Us[128 * NE];     // s-rows
    __shared__ float Zs[4][128];

    const int b   = blockIdx.z;
    const int tt0 = blockIdx.y * 128;
    const int ss0 = blockIdx.x * 128;
    const int tid  = threadIdx.x;
    const int warp = tid >> 5, lane = tid & 31;
    const int r  = lane >> 2;          // 0..7
    const int c2 = (lane & 3) * 2;     // 0,2,4,6

    const uint4* Xsrc = (const uint4*)(g_Xh + ((size_t)b * TT + tt0) * NE);
    const uint4* Usrc = (const uint4*)(g_Uh + ((size_t)b * TT + ss0) * NE);
    ((uint4*)Xs)[tid]       = Xsrc[tid];
    ((uint4*)Xs)[tid + 128] = Xsrc[tid + 128];
    ((uint4*)Us)[tid]       = Usrc[tid];
    ((uint4*)Us)[tid + 128] = Usrc[tid + 128];
    __syncthreads();

    uint64_t zacc[16];
#pragma unroll
    for (int nt = 0; nt < 16; ++nt) zacc[nt] = pk2(0.f, 0.f);

#pragma unroll
    for (int mt = 0; mt < 2; ++mt) {
        const int row = warp * 32 + mt * 16 + r;
        uint32_t a0 = *(const uint32_t*)(Xs + row * NE + c2);
        uint32_t a1 = *(const uint32_t*)(Xs + (row + 8) * NE + c2);
        uint32_t a2 = *(const uint32_t*)(Xs + row * NE + c2 + 8);
        uint32_t a3 = *(const uint32_t*)(Xs + (row + 8) * NE + c2 + 8);

#pragma unroll
        for (int nt = 0; nt < 16; ++nt) {
            const int n = nt * 8 + r;
            uint32_t b0 = *(const uint32_t*)(Us + n * NE + c2);
            uint32_t b1 = *(const uint32_t*)(Us + n * NE + c2 + 8);
            float f0 = 0.f, f1 = 0.f, f2 = 0.f, f3 = 0.f;
            asm volatile(
                "mma.sync.aligned.m16n8k16.row.col.f32.f16.f16.f32 "
                "{%0,%1,%2,%3}, {%4,%5,%6,%7}, {%8,%9}, {%0,%1,%2,%3};"
                : "+f"(f0), "+f"(f1), "+f"(f2), "+f"(f3)
                : "r"(a0), "r"(a1), "r"(a2), "r"(a3), "r"(b0), "r"(b1));
            zacc[nt] = add2_(zacc[nt], add2_(ev2(f0, f1), ev2(f2, f3)));
        }
    }

    // Reduce column sums across the 8 lanes sharing (lane&3)
#pragma unroll
    for (int nt = 0; nt < 16; ++nt) {
        float zx, zy; up2(zacc[nt], zx, zy);
#pragma unroll
        for (int off = 4; off <= 16; off <<= 1) {
            zx += __shfl_xor_sync(0xffffffffu, zx, off);
            zy += __shfl_xor_sync(0xffffffffu, zy, off);
        }
        if (lane < 4) {
            Zs[warp][nt * 8 + lane * 2]     = zx;
            Zs[warp][nt * 8 + lane * 2 + 1] = zy;
        }
    }
    __syncthreads();
    g_Zpart[((size_t)b * 32 + blockIdx.y) * TT + ss0 + tid] =
        (Zs[0][tid] + Zs[1][tid]) + (Zs[2][tid] + Zs[3][tid]);
}

// ---------------------------------------------------------------------------
// Kernel 3: Z[b,s] = sum of 32 partials (fixed order);
//           XZh[b,e,s] = fp16( x[b,s,e] / Z[b,s] )
__global__ void __launch_bounds__(128) z_kernel(const float* __restrict__ x) {
    int gs = blockIdx.x * 128 + threadIdx.x;   // b*T + s
    int b  = gs >> 12;
    int s  = gs & (TT - 1);
    float z = 0.f;
#pragma unroll
    for (int j = 0; j < 32; ++j)
        z += g_Zpart[((size_t)b * 32 + j) * TT + s];
    float inv = 1.0f / z;
#pragma unroll
    for (int e = 0; e < NE; ++e)
        g_XZh[((size_t)b * NE + e) * TT + s] =
            __float2half_rn(x[(size_t)gs * NE + e] * inv);
}

// ---------------------------------------------------------------------------
// Kernel 4 (pass B'): recompute E tile in registers (mma1 -> poly -> half2)
// feeding mma2 directly (fragment identity). 64 t-rows per block (one m16 per
// warp), s-range split in halves across blockIdx.y; partial G -> g_Gpart.
// grid = (64 t-tiles, 2 s-halves, B), block = 128 = 4 warps.
__global__ void __launch_bounds__(128) passB_kernel() {
    __shared__ __align__(16) __half Xs[64 * NE];
    __shared__ __align__(16) __half Us[2][128 * NE];      // s-chunk U tiles
    __shared__ __align__(16) __half XZs[2][NE * 136];     // [e][s] tiles, stride 136
    __shared__ float Gs[64 * 17];

    const int b   = blockIdx.z;
    const int sh  = blockIdx.y;          // s-half: 0 or 1
    const int tt  = blockIdx.x;          // 64-row t-tile
    const int t0  = tt * 64;
    const int sbase = sh * 2048;
    const int tid = threadIdx.x;
    const int warp = tid >> 5, lane = tid & 31;
    const int r  = lane >> 2;
    const int c2 = (lane & 3) * 2;

    {
        const uint4* Xsrc = (const uint4*)(g_Xh + ((size_t)b * TT + t0) * NE);
        ((uint4*)Xs)[tid] = Xsrc[tid];   // 64 rows x 32B = exactly 128 uint4
    }
    __syncthreads();

    // A fragment of mma1 (X rows), loaded once: one m16 per warp
    uint32_t xa0, xa1, xa2, xa3;
    {
        int row = warp * 16 + r;
        xa0 = *(const uint32_t*)(Xs + row * NE + c2);
        xa1 = *(const uint32_t*)(Xs + (row + 8) * NE + c2);
        xa2 = *(const uint32_t*)(Xs + row * NE + c2 + 8);
        xa3 = *(const uint32_t*)(Xs + (row + 8) * NE + c2 + 8);
    }

    float acc[2][4];
#pragma unroll
    for (int ne = 0; ne < 2; ++ne)
#pragma unroll
        for (int q = 0; q < 4; ++q) acc[ne][q] = 0.f;

    const __half* Ub  = g_Uh + (size_t)b * TT * NE;
    const __half* XZb = g_XZh + (size_t)b * NE * TT;
    const uint32_t UsB = (uint32_t)__cvta_generic_to_shared(&Us[0][0]);
    const uint32_t XZB = (uint32_t)__cvta_generic_to_shared(&XZs[0][0]);

    auto stage = [&](int buf, int sc) {
        const int sg = sbase + sc;
        // U: 128 rows x 32B = 256 x 16B chunks
#pragma unroll
        for (int q = 0; q < 2; ++q) {
            int i = q * 128 + tid;
            int row = i >> 1, c = i & 1;
            cp16(UsB + buf * 4096 + row * 32 + c * 16,
                 Ub + (size_t)(sg + row) * NE + c * 8);
        }
        // XZ: 16 e-rows x 128 halves = 256 x 16B chunks, dst stride 272B
#pragma unroll
        for (int q = 0; q < 2; ++q) {
            int j = q * 128 + tid;
            int e = j >> 4, c = j & 15;
            cp16(XZB + buf * 4352 + e * 272 + c * 16,
                 XZb + (size_t)e * TT + sg + c * 8);
        }
    };

    stage(0, 0);
    cp_commit();

    for (int sc = 0; sc < 2048; sc += 128) {
        const int buf = (sc >> 7) & 1;
        if (sc + 128 < 2048) {
            stage(buf ^ 1, sc + 128);
            cp_commit();
            cp_wait1();
        } else {
            cp_wait0();
        }
        __syncthreads();

        const __half* Ubuf = Us[buf];
        const __half* Zbuf = XZs[buf];

#pragma unroll
        for (int ss = 0; ss < 8; ++ss) {
            const int s0 = ss * 16;
            // mma1 B fragments (U, col-major k=e)
            uint32_t ub0[2], ub1[2];
#pragma unroll
            for (int nt = 0; nt < 2; ++nt) {
                int n = s0 + nt * 8 + r;
                ub0[nt] = *(const uint32_t*)(Ubuf + n * NE + c2);
                ub1[nt] = *(const uint32_t*)(Ubuf + n * NE + c2 + 8);
            }
            // mma2 B fragments (XZ, col-major k=s, n=e)
            uint32_t vb0[2], vb1[2];
#pragma unroll
            for (int ne = 0; ne < 2; ++ne) {
                int n = ne * 8 + r;
                vb0[ne] = *(const uint32_t*)(Zbuf + n * 136 + s0 + c2);
                vb1[ne] = *(const uint32_t*)(Zbuf + n * 136 + s0 + c2 + 8);
            }

            float f[2][4];
#pragma unroll
            for (int nt = 0; nt < 2; ++nt) {
                f[nt][0] = 0.f; f[nt][1] = 0.f; f[nt][2] = 0.f; f[nt][3] = 0.f;
                asm volatile(
                    "mma.sync.aligned.m16n8k16.row.col.f32.f16.f16.f32 "
                    "{%0,%1,%2,%3}, {%4,%5,%6,%7}, {%8,%9}, {%0,%1,%2,%3};"
                    : "+f"(f[nt][0]), "+f"(f[nt][1]), "+f"(f[nt][2]), "+f"(f[nt][3])
                    : "r"(xa0), "r"(xa1), "r"(xa2), "r"(xa3),
                      "r"(ub0[nt]), "r"(ub1[nt]));
            }
            // E fragment = A fragment of mma2 (layout identity)
            uint32_t ea0 = ev2h(f[0][0], f[0][1]);
            uint32_t ea1 = ev2h(f[0][2], f[0][3]);
            uint32_t ea2 = ev2h(f[1][0], f[1][1]);
            uint32_t ea3 = ev2h(f[1][2], f[1][3]);
#pragma unroll
            for (int ne = 0; ne < 2; ++ne) {
                asm volatile(
                    "mma.sync.aligned.m16n8k16.row.col.f32.f16.f16.f32 "
                    "{%0,%1,%2,%3}, {%4,%5,%6,%7}, {%8,%9}, {%0,%1,%2,%3};"
                    : "+f"(acc[ne][0]), "+f"(acc[ne][1]),
                      "+f"(acc[ne][2]), "+f"(acc[ne][3])
                    : "r"(ea0), "r"(ea1), "r"(ea2), "r"(ea3),
                      "r"(vb0[ne]), "r"(vb1[ne]));
            }
        }
        __syncthreads();
    }

    // Spill G fragments to smem
    {
        int rr = warp * 16 + (lane >> 2);
#pragma unroll
        for (int ne = 0; ne < 2; ++ne) {
            int c = ne * 8 + (lane & 3) * 2;
            Gs[rr * 17 + c]           = acc[ne][0];
            Gs[rr * 17 + c + 1]       = acc[ne][1];
            Gs[(rr + 8) * 17 + c]     = acc[ne][2];
            Gs[(rr + 8) * 17 + c + 1] = acc[ne][3];
        }
    }
    __syncthreads();

    // Write partial G tile (64 x 16 fp32, linear)
    {
        float* dst = g_Gpart + ((size_t)((b * 2 + sh) * 64 + tt)) * (64 * NE);
        for (int i = tid; i < 64 * NE; i += 128)
            dst[i] = Gs[(i >> 4) * 17 + (i & 15)];
    }
}

// ---------------------------------------------------------------------------
// Kernel 5: combine the two s-half partials (fixed order) and apply @Wk.
// grid = (64 t-tiles, B), block = 128.
__global__ void __launch_bounds__(128) out_kernel(const float* __restrict__ Wk,
                                                  float* __restrict__ out) {
    __shared__ float Gsum[64 * 17];
    __shared__ float wks[NE * HH];

    const int b  = blockIdx.y;
    const int tt = blockIdx.x;
    const int tid = threadIdx.x;

    for (int i = tid; i < NE * HH; i += 128) wks[i] = Wk[i];
    {
        const float* g0 = g_Gpart + ((size_t)((b * 2 + 0) * 64 + tt)) * (64 * NE);
        const float* g1 = g_Gpart + ((size_t)((b * 2 + 1) * 64 + tt)) * (64 * NE);
        for (int i = tid; i < 64 * NE; i += 128)
            Gsum[(i >> 4) * 17 + (i & 15)] = g0[i] + g1[i];
    }
    __syncthreads();

    for (int idx = tid; idx < 64 * HH; idx += 128) {
        int rr = idx >> 6, h = idx & 63;
        float sum = 0.f;
#pragma unroll
        for (int e = 0; e < NE; ++e) sum += Gsum[rr * 17 + e] * wks[e * HH + h];
        out[((size_t)(b * TT + tt * 64 + rr)) * HH + h] = sum;
    }
}

// ---------------------------------------------------------------------------
extern "C" void kernel_launch(void* const* d_in, const int* in_sizes, int n_in,
                              void* d_out, int out_size) {
    const float* x  = (const float*)d_in[0];   // [B, T, 16]
    const float* Wq = (const float*)d_in[1];   // [16, 64]
    const float* Wk = (const float*)d_in[2];   // [16, 64]
    // d_in[3] = Wv, unused (reference uses Wk for values)
    float* out = (float*)d_out;                // [B, T, 64]

    u_kernel<<<(BB * TT) / 128, 128>>>(x, Wq, Wk);
    passA_kernel<<<dim3(32, 32, BB), 128>>>();
    z_kernel<<<(BB * TT) / 128, 128>>>(x);
    passB_kernel<<<dim3(64, 2, BB), 128>>>();
    out_kernel<<<dim3(64, BB), 128>>>(Wk, out);
}

// round 8
// speedup vs baseline: 5.7741x; 1.0590x over previous
#include <cuda_runtime.h>
#include <cuda_fp16.h>
#include <cstdint>

// Problem constants
#define BB 8
#define TT 4096
#define NE 16
#define HH 64

// Scratch (device globals: allocation-free per harness rules)
__device__ __half g_Uh[BB * TT * NE];                 // fp16 U[b,s,e]
__device__ __half g_Xh[BB * TT * NE];                 // fp16 x[b,t,e]
__device__ float  g_Zpart[BB * 32 * TT];              // per-t-tile column sums of E
__device__ __half g_XZh[BB * NE * TT];                // [b][e][s] = x/Z (fp16, transposed)
__device__ float  g_Gpart[BB * 4 * 32 * 128 * NE];    // partial G tiles (4-way s-split)

// ---------------------------------------------------------------------------
// f32x2 packed helpers (FFMA2: PTX-only, ptxas won't auto-fuse)
__device__ __forceinline__ uint64_t pk2(float a, float b) {
    uint64_t r; asm("mov.b64 %0, {%1, %2};" : "=l"(r) : "f"(a), "f"(b)); return r;
}
__device__ __forceinline__ void up2(uint64_t v, float& a, float& b) {
    asm("mov.b64 {%0, %1}, %2;" : "=f"(a), "=f"(b) : "l"(v));
}
__device__ __forceinline__ uint64_t fma2_(uint64_t a, uint64_t b, uint64_t c) {
    uint64_t r; asm("fma.rn.f32x2 %0, %1, %2, %3;" : "=l"(r) : "l"(a), "l"(b), "l"(c)); return r;
}
__device__ __forceinline__ uint64_t add2_(uint64_t a, uint64_t b) {
    uint64_t r; asm("add.rn.f32x2 %0, %1, %2;" : "=l"(r) : "l"(a), "l"(b)); return r;
}

// ev = exp(d^(-1/16)) via cubic in w = log2(d), Chebyshev-fit on w in [2, 8.5]
// (d in [4, 362]; actual d range ~[9, 170]). Max abs err ~5e-5 (rel ~2.3e-5).
__device__ __forceinline__ uint64_t ev2(float d0, float d1) {
    uint64_t w = pk2(__log2f(d0), __log2f(d1));
    uint64_t r = fma2_(w, pk2(-9.745e-5f, -9.745e-5f), pk2(0.0045432f, 0.0045432f));
    r = fma2_(r, w, pk2(-0.1161814f, -0.1161814f));
    r = fma2_(r, w, pk2(2.7167135f, 2.7167135f));
    return r;
}
__device__ __forceinline__ uint32_t ev2h(float d0, float d1) {
    float lo, hi; up2(ev2(d0, d1), lo, hi);
    __half2 h = __floats2half2_rn(lo, hi);
    return *(uint32_t*)&h;
}

// cp.async helpers
__device__ __forceinline__ void cp16(uint32_t dst, const void* src) {
    asm volatile("cp.async.cg.shared.global [%0], [%1], 16;\n" :: "r"(dst), "l"(src));
}
__device__ __forceinline__ void cp_commit() { asm volatile("cp.async.commit_group;\n"); }
__device__ __forceinline__ void cp_wait1()  { asm volatile("cp.async.wait_group 1;\n" ::: "memory"); }
__device__ __forceinline__ void cp_wait0()  { asm volatile("cp.async.wait_group 0;\n" ::: "memory"); }

// ---------------------------------------------------------------------------
// Kernel 1 (merged m+u): M = Wq@Wk^T in smem, then U[b,s,:] = M @ x[b,s,:]
// (fp16 out); also x -> fp16.
__global__ void __launch_bounds__(128) u_kernel(const float* __restrict__ x,
                                                const float* __restrict__ Wq,
                                                const float* __restrict__ Wk) {
    __shared__ float Ms[NE * NE];
#pragma unroll
    for (int j = 0; j < 2; ++j) {
        int idx = threadIdx.x * 2 + j;
        int e = idx >> 4, e2 = idx & 15;
        float s = 0.f;
#pragma unroll
        for (int h = 0; h < HH; ++h)
            s += Wq[e * HH + h] * Wk[e2 * HH + h];
        Ms[idx] = s;
    }
    __syncthreads();

    int gs = blockIdx.x * 128 + threadIdx.x;   // 0 .. B*T-1
    float xv[NE];
    const float4* xp = (const float4*)(x + (size_t)gs * NE);
#pragma unroll
    for (int q = 0; q < 4; ++q) {
        float4 v = xp[q];
        xv[q * 4 + 0] = v.x; xv[q * 4 + 1] = v.y;
        xv[q * 4 + 2] = v.z; xv[q * 4 + 3] = v.w;
    }
#pragma unroll
    for (int e = 0; e < NE; ++e)
        g_Xh[(size_t)gs * NE + e] = __float2half_rn(xv[e]);
#pragma unroll
    for (int j = 0; j < NE; ++j) {
        float u = 0.f;
#pragma unroll
        for (int k = 0; k < NE; ++k) u += Ms[j * NE + k] * xv[k];
        g_Uh[(size_t)gs * NE + j] = __float2half_rn(u);
    }
}

// ---------------------------------------------------------------------------
// Kernel 2 (pass A'): column sums of E only (no E store). nt-outer / mt-inner
// so B-fragment LDS amortize over both m-tiles.
// grid = (s_tiles=32, t_tiles=32, B), block = 128 (4 warps x 32 t-rows each).
__global__ void __launch_bounds__(128) passA_kernel() {
    __shared__ __align__(16) __half Xs[128 * NE];     // t-rows
    __shared__ __align__(16) __half Us[128 * NE];     // s-rows
    __shared__ float Zs[4][128];

    const int b   = blockIdx.z;
    const int tt0 = blockIdx.y * 128;
    const int ss0 = blockIdx.x * 128;
    const int tid  = threadIdx.x;
    const int warp = tid >> 5, lane = tid & 31;
    const int r  = lane >> 2;          // 0..7
    const int c2 = (lane & 3) * 2;     // 0,2,4,6

    const uint4* Xsrc = (const uint4*)(g_Xh + ((size_t)b * TT + tt0) * NE);
    const uint4* Usrc = (const uint4*)(g_Uh + ((size_t)b * TT + ss0) * NE);
    ((uint4*)Xs)[tid]       = Xsrc[tid];
    ((uint4*)Xs)[tid + 128] = Xsrc[tid + 128];
    ((uint4*)Us)[tid]       = Usrc[tid];
    ((uint4*)Us)[tid + 128] = Usrc[tid + 128];
    __syncthreads();

    // A fragments for both m-tiles, loaded once
    uint32_t xa[2][4];
#pragma unroll
    for (int mt = 0; mt < 2; ++mt) {
        const int row = warp * 32 + mt * 16 + r;
        xa[mt][0] = *(const uint32_t*)(Xs + row * NE + c2);
        xa[mt][1] = *(const uint32_t*)(Xs + (row + 8) * NE + c2);
        xa[mt][2] = *(const uint32_t*)(Xs + row * NE + c2 + 8);
        xa[mt][3] = *(const uint32_t*)(Xs + (row + 8) * NE + c2 + 8);
    }

    uint64_t zacc[16];
#pragma unroll
    for (int nt = 0; nt < 16; ++nt) zacc[nt] = pk2(0.f, 0.f);

#pragma unroll
    for (int nt = 0; nt < 16; ++nt) {
        const int n = nt * 8 + r;
        uint32_t b0 = *(const uint32_t*)(Us + n * NE + c2);
        uint32_t b1 = *(const uint32_t*)(Us + n * NE + c2 + 8);
#pragma unroll
        for (int mt = 0; mt < 2; ++mt) {
            float f0 = 0.f, f1 = 0.f, f2 = 0.f, f3 = 0.f;
            asm volatile(
                "mma.sync.aligned.m16n8k16.row.col.f32.f16.f16.f32 "
                "{%0,%1,%2,%3}, {%4,%5,%6,%7}, {%8,%9}, {%0,%1,%2,%3};"
                : "+f"(f0), "+f"(f1), "+f"(f2), "+f"(f3)
                : "r"(xa[mt][0]), "r"(xa[mt][1]), "r"(xa[mt][2]), "r"(xa[mt][3]),
                  "r"(b0), "r"(b1));
            zacc[nt] = add2_(zacc[nt], add2_(ev2(f0, f1), ev2(f2, f3)));
        }
    }

    // Reduce column sums across the 8 lanes sharing (lane&3)
#pragma unroll
    for (int nt = 0; nt < 16; ++nt) {
        float zx, zy; up2(zacc[nt], zx, zy);
#pragma unroll
        for (int off = 4; off <= 16; off <<= 1) {
            zx += __shfl_xor_sync(0xffffffffu, zx, off);
            zy += __shfl_xor_sync(0xffffffffu, zy, off);
        }
        if (lane < 4) {
            Zs[warp][nt * 8 + lane * 2]     = zx;
            Zs[warp][nt * 8 + lane * 2 + 1] = zy;
        }
    }
    __syncthreads();
    g_Zpart[((size_t)b * 32 + blockIdx.y) * TT + ss0 + tid] =
        (Zs[0][tid] + Zs[1][tid]) + (Zs[2][tid] + Zs[3][tid]);
}

// ---------------------------------------------------------------------------
// Kernel 3: Z[b,s] = sum of 32 partials (fixed order);
//           XZh[b,e,s] = fp16( x[b,s,e] / Z[b,s] )
__global__ void __launch_bounds__(128) z_kernel(const float* __restrict__ x) {
    int gs = blockIdx.x * 128 + threadIdx.x;   // b*T + s
    int b  = gs >> 12;
    int s  = gs & (TT - 1);
    float z = 0.f;
#pragma unroll
    for (int j = 0; j < 32; ++j)
        z += g_Zpart[((size_t)b * 32 + j) * TT + s];
    float inv = 1.0f / z;
#pragma unroll
    for (int e = 0; e < NE; ++e)
        g_XZh[((size_t)b * NE + e) * TT + s] =
            __float2half_rn(x[(size_t)gs * NE + e] * inv);
}

// ---------------------------------------------------------------------------
// Kernel 4 (pass B'): recompute E (mma1 -> poly -> half2) feeding mma2
// directly. 128 t-rows per block (2 m16 per warp, amortizing B-frag loads),
// s-range split 4 ways across blockIdx.y; partial G -> g_Gpart.
// grid = (32 t-tiles, 4 s-quarters, B), block = 128 = 4 warps.
__global__ void __launch_bounds__(128) passB_kernel() {
    __shared__ __align__(16) __half Xs[128 * NE];
    __shared__ __align__(16) __half Us[2][128 * NE];      // s-chunk U tiles
    __shared__ __align__(16) __half XZs[2][NE * 136];     // [e][s] tiles, stride 136
    __shared__ float Gs[128 * 17];

    const int b   = blockIdx.z;
    const int sh  = blockIdx.y;          // s-quarter: 0..3
    const int tt  = blockIdx.x;          // 128-row t-tile
    const int t0  = tt * 128;
    const int sbase = sh * 1024;
    const int tid = threadIdx.x;
    const int warp = tid >> 5, lane = tid & 31;
    const int r  = lane >> 2;
    const int c2 = (lane & 3) * 2;

    {
        const uint4* Xsrc = (const uint4*)(g_Xh + ((size_t)b * TT + t0) * NE);
        ((uint4*)Xs)[tid]       = Xsrc[tid];
        ((uint4*)Xs)[tid + 128] = Xsrc[tid + 128];
    }
    __syncthreads();

    // A fragments of mma1 (X rows), loaded once: two m16 per warp
    uint32_t xa[2][4];
#pragma unroll
    for (int mt = 0; mt < 2; ++mt) {
        int row = warp * 32 + mt * 16 + r;
        xa[mt][0] = *(const uint32_t*)(Xs + row * NE + c2);
        xa[mt][1] = *(const uint32_t*)(Xs + (row + 8) * NE + c2);
        xa[mt][2] = *(const uint32_t*)(Xs + row * NE + c2 + 8);
        xa[mt][3] = *(const uint32_t*)(Xs + (row + 8) * NE + c2 + 8);
    }

    float acc[2][2][4];
#pragma unroll
    for (int mt = 0; mt < 2; ++mt)
#pragma unroll
        for (int ne = 0; ne < 2; ++ne)
#pragma unroll
            for (int q = 0; q < 4; ++q) acc[mt][ne][q] = 0.f;

    const __half* Ub  = g_Uh + (size_t)b * TT * NE;
    const __half* XZb = g_XZh + (size_t)b * NE * TT;
    const uint32_t UsB = (uint32_t)__cvta_generic_to_shared(&Us[0][0]);
    const uint32_t XZB = (uint32_t)__cvta_generic_to_shared(&XZs[0][0]);

    auto stage = [&](int buf, int sc) {
        const int sg = sbase + sc;
        // U: 128 rows x 32B = 256 x 16B chunks
#pragma unroll
        for (int q = 0; q < 2; ++q) {
            int i = q * 128 + tid;
            int row = i >> 1, c = i & 1;
            cp16(UsB + buf * 4096 + row * 32 + c * 16,
                 Ub + (size_t)(sg + row) * NE + c * 8);
        }
        // XZ: 16 e-rows x 128 halves = 256 x 16B chunks, dst stride 272B
#pragma unroll
        for (int q = 0; q < 2; ++q) {
            int j = q * 128 + tid;
            int e = j >> 4, c = j & 15;
            cp16(XZB + buf * 4352 + e * 272 + c * 16,
                 XZb + (size_t)e * TT + sg + c * 8);
        }
    };

    stage(0, 0);
    cp_commit();

    for (int sc = 0; sc < 1024; sc += 128) {
        const int buf = (sc >> 7) & 1;
        if (sc + 128 < 1024) {
            stage(buf ^ 1, sc + 128);
            cp_commit();
            cp_wait1();
        } else {
            cp_wait0();
        }
        __syncthreads();

        const __half* Ubuf = Us[buf];
        const __half* Zbuf = XZs[buf];

#pragma unroll
        for (int ss = 0; ss < 8; ++ss) {
            const int s0 = ss * 16;
            // mma1 B fragments (U, col-major k=e)
            uint32_t ub0[2], ub1[2];
#pragma unroll
            for (int nt = 0; nt < 2; ++nt) {
                int n = s0 + nt * 8 + r;
                ub0[nt] = *(const uint32_t*)(Ubuf + n * NE + c2);
                ub1[nt] = *(const uint32_t*)(Ubuf + n * NE + c2 + 8);
            }
            // mma2 B fragments (XZ, col-major k=s, n=e)
            uint32_t vb0[2], vb1[2];
#pragma unroll
            for (int ne = 0; ne < 2; ++ne) {
                int n = ne * 8 + r;
                vb0[ne] = *(const uint32_t*)(Zbuf + n * 136 + s0 + c2);
                vb1[ne] = *(const uint32_t*)(Zbuf + n * 136 + s0 + c2 + 8);
            }

#pragma unroll
            for (int mt = 0; mt < 2; ++mt) {
                float f[2][4];
#pragma unroll
                for (int nt = 0; nt < 2; ++nt) {
                    f[nt][0] = 0.f; f[nt][1] = 0.f; f[nt][2] = 0.f; f[nt][3] = 0.f;
                    asm volatile(
                        "mma.sync.aligned.m16n8k16.row.col.f32.f16.f16.f32 "
                        "{%0,%1,%2,%3}, {%4,%5,%6,%7}, {%8,%9}, {%0,%1,%2,%3};"
                        : "+f"(f[nt][0]), "+f"(f[nt][1]), "+f"(f[nt][2]), "+f"(f[nt][3])
                        : "r"(xa[mt][0]), "r"(xa[mt][1]), "r"(xa[mt][2]), "r"(xa[mt][3]),
                          "r"(ub0[nt]), "r"(ub1[nt]));
                }
                // E fragment = A fragment of mma2 (layout identity)
                uint32_t ea0 = ev2h(f[0][0], f[0][1]);
                uint32_t ea1 = ev2h(f[0][2], f[0][3]);
                uint32_t ea2 = ev2h(f[1][0], f[1][1]);
                uint32_t ea3 = ev2h(f[1][2], f[1][3]);
#pragma unroll
                for (int ne = 0; ne < 2; ++ne) {
                    asm volatile(
                        "mma.sync.aligned.m16n8k16.row.col.f32.f16.f16.f32 "
                        "{%0,%1,%2,%3}, {%4,%5,%6,%7}, {%8,%9}, {%0,%1,%2,%3};"
                        : "+f"(acc[mt][ne][0]), "+f"(acc[mt][ne][1]),
                          "+f"(acc[mt][ne][2]), "+f"(acc[mt][ne][3])
                        : "r"(ea0), "r"(ea1), "r"(ea2), "r"(ea3),
                          "r"(vb0[ne]), "r"(vb1[ne]));
                }
            }
        }
        __syncthreads();
    }

    // Spill G fragments to smem
#pragma unroll
    for (int mt = 0; mt < 2; ++mt) {
        int rr = warp * 32 + mt * 16 + (lane >> 2);
#pragma unroll
        for (int ne = 0; ne < 2; ++ne) {
            int c = ne * 8 + (lane & 3) * 2;
            Gs[rr * 17 + c]           = acc[mt][ne][0];
            Gs[rr * 17 + c + 1]       = acc[mt][ne][1];
            Gs[(rr + 8) * 17 + c]     = acc[mt][ne][2];
            Gs[(rr + 8) * 17 + c + 1] = acc[mt][ne][3];
        }
    }
    __syncthreads();

    // Write partial G tile (128 x 16 fp32, linear)
    {
        float* dst = g_Gpart + ((size_t)((b * 4 + sh) * 32 + tt)) * (128 * NE);
        for (int i = tid; i < 128 * NE; i += 128)
            dst[i] = Gs[(i >> 4) * 17 + (i & 15)];
    }
}

// ---------------------------------------------------------------------------
// Kernel 5: combine the four s-quarter partials (fixed order) and apply @Wk.
// grid = (32 t-tiles, B), block = 128.
__global__ void __launch_bounds__(128) out_kernel(const float* __restrict__ Wk,
                                                  float* __restrict__ out) {
    __shared__ float Gsum[128 * 17];
    __shared__ float wks[NE * HH];

    const int b  = blockIdx.y;
    const int tt = blockIdx.x;
    const int tid = threadIdx.x;

    for (int i = tid; i < NE * HH; i += 128) wks[i] = Wk[i];
    {
        const float* g0 = g_Gpart + ((size_t)((b * 4 + 0) * 32 + tt)) * (128 * NE);
        const float* g1 = g_Gpart + ((size_t)((b * 4 + 1) * 32 + tt)) * (128 * NE);
        const float* g2 = g_Gpart + ((size_t)((b * 4 + 2) * 32 + tt)) * (128 * NE);
        const float* g3 = g_Gpart + ((size_t)((b * 4 + 3) * 32 + tt)) * (128 * NE);
        for (int i = tid; i < 128 * NE; i += 128)
            Gsum[(i >> 4) * 17 + (i & 15)] = (g0[i] + g1[i]) + (g2[i] + g3[i]);
    }
    __syncthreads();

    for (int idx = tid; idx < 128 * HH; idx += 128) {
        int rr = idx >> 6, h = idx & 63;
        float sum = 0.f;
#pragma unroll
        for (int e = 0; e < NE; ++e) sum += Gsum[rr * 17 + e] * wks[e * HH + h];
        out[((size_t)(b * TT + tt * 128 + rr)) * HH + h] = sum;
    }
}

// ---------------------------------------------------------------------------
extern "C" void kernel_launch(void* const* d_in, const int* in_sizes, int n_in,
                              void* d_out, int out_size) {
    const float* x  = (const float*)d_in[0];   // [B, T, 16]
    const float* Wq = (const float*)d_in[1];   // [16, 64]
    const float* Wk = (const float*)d_in[2];   // [16, 64]
    // d_in[3] = Wv, unused (reference uses Wk for values)
    float* out = (float*)d_out;                // [B, T, 64]

    u_kernel<<<(BB * TT) / 128, 128>>>(x, Wq, Wk);
    passA_kernel<<<dim3(32, 32, BB), 128>>>();
    z_kernel<<<(BB * TT) / 128, 128>>>(x);
    passB_kernel<<<dim3(32, 4, BB), 128>>>();
    out_kernel<<<dim3(32, BB), 128>>>(Wk, out);
}